// round 1
// baseline (speedup 1.0000x reference)
#include <cuda_runtime.h>

// ---------------------------------------------------------------------------
// Attention_21474836480706: B=4, N=1024, H=16, D=72, HID=1152 (fp32)
//   qkv = x @ w_qkv + b_qkv ; split -> Q,K,V [B,H,N,D]
//   att = softmax(Q K^T / sqrt(D)) ; O = att @ V -> [B,N,H*D]
//   out = O @ w_out + b_out
// Round 1 baseline: fp32 SIMT tiled GEMMs + row softmax, scratch in
// __device__ globals (no allocations, graph-capturable).
// ---------------------------------------------------------------------------

namespace {
constexpr int Bb    = 4;
constexpr int Nn    = 1024;
constexpr int Hh    = 16;
constexpr int Dd    = 72;
constexpr int HID   = 1152;
constexpr int ATT   = Hh * Dd;        // 1152
constexpr int MTOK  = Bb * Nn;        // 4096
constexpr int QKVN  = 3 * ATT;        // 3456
constexpr int BHEAD = Bb * Hh;        // 64
}

// Scratch (module-load allocated; no runtime allocation)
__device__ float g_q[(size_t)BHEAD * Nn * Dd];        // 18.9 MB
__device__ float g_k[(size_t)BHEAD * Nn * Dd];        // 18.9 MB
__device__ float g_v[(size_t)BHEAD * Nn * Dd];        // 18.9 MB
__device__ float g_s[(size_t)BHEAD * Nn * Nn];        // 256 MB (S / P matrix)
__device__ float g_o[(size_t)MTOK * HID];             // 18.9 MB (att output, [B,N,H*D])

// ---------------------------------------------------------------------------
// Kernel 1: QKV projection. C[4096,3456] = X[4096,1152] @ W[1152,3456] + bias,
// epilogue scatters into head-major Q/K/V.
// 128x128x8 tile, 8x8 microtile, 256 threads.
// ---------------------------------------------------------------------------
__global__ __launch_bounds__(256) void k_qkv(const float* __restrict__ A,
                                             const float* __restrict__ W,
                                             const float* __restrict__ bias) {
    constexpr int BM = 128, BN = 128, BK = 8, TM = 8, TN = 8;
    __shared__ float As[BK][BM];
    __shared__ float Bs[BK][BN];

    const int tid  = threadIdx.x;
    const int row0 = blockIdx.y * BM;
    const int col0 = blockIdx.x * BN;
    const int arow = tid >> 1, acol = (tid & 1) * 4;
    const int brow = tid >> 5, bcol = (tid & 31) * 4;
    const int tr = (tid >> 4) * TM;
    const int tc = (tid & 15) * TN;

    float acc[TM][TN] = {};
    float ra[TM], rb[TN];

    for (int k0 = 0; k0 < HID; k0 += BK) {
        float4 a4 = *reinterpret_cast<const float4*>(&A[(size_t)(row0 + arow) * HID + k0 + acol]);
        As[acol + 0][arow] = a4.x;
        As[acol + 1][arow] = a4.y;
        As[acol + 2][arow] = a4.z;
        As[acol + 3][arow] = a4.w;
        float4 b4 = *reinterpret_cast<const float4*>(&W[(size_t)(k0 + brow) * QKVN + col0 + bcol]);
        *reinterpret_cast<float4*>(&Bs[brow][bcol]) = b4;
        __syncthreads();
#pragma unroll
        for (int k = 0; k < BK; ++k) {
#pragma unroll
            for (int m = 0; m < TM; ++m) ra[m] = As[k][tr + m];
#pragma unroll
            for (int n = 0; n < TN; ++n) rb[n] = Bs[k][tc + n];
#pragma unroll
            for (int m = 0; m < TM; ++m)
#pragma unroll
                for (int n = 0; n < TN; ++n) acc[m][n] = fmaf(ra[m], rb[n], acc[m][n]);
        }
        __syncthreads();
    }

#pragma unroll
    for (int m = 0; m < TM; ++m) {
        const int r   = row0 + tr + m;
        const int b   = r >> 10;       // / 1024
        const int tok = r & 1023;
#pragma unroll
        for (int n = 0; n < TN; ++n) {
            const int c = col0 + tc + n;
            const float v = acc[m][n] + bias[c];
            const int which = c / ATT;
            const int rem   = c - which * ATT;
            const int h     = rem / Dd;
            const int d     = rem - h * Dd;
            float* dst = (which == 0) ? g_q : (which == 1) ? g_k : g_v;
            dst[(((size_t)(b * Hh + h) * Nn) + tok) * Dd + d] = v;
        }
    }
}

// ---------------------------------------------------------------------------
// Kernel 2: S = (Q K^T) * scale per (b,h). 64x64 tile, full K=72 in smem.
// Smem stored k-major ([k][row]) so fragment reads are conflict-free.
// ---------------------------------------------------------------------------
__global__ __launch_bounds__(256) void k_qkt() {
    constexpr int BM = 64, BN = 64;
    __shared__ float Qs[Dd][BM];
    __shared__ float Ks[Dd][BN];

    const int bh = blockIdx.z;
    const float* Q = g_q + (size_t)bh * Nn * Dd;
    const float* K = g_k + (size_t)bh * Nn * Dd;
    const int m0 = blockIdx.y * BM;
    const int n0 = blockIdx.x * BN;
    const int tid = threadIdx.x;

    for (int idx = tid; idx < BM * Dd; idx += 256) {
        const int r = idx / Dd;
        const int c = idx - r * Dd;
        Qs[c][r] = Q[(size_t)(m0 + r) * Dd + c];
        Ks[c][r] = K[(size_t)(n0 + r) * Dd + c];
    }
    __syncthreads();

    const int tr = (tid >> 4) * 4;
    const int tc = (tid & 15) * 4;
    float acc[4][4] = {};
#pragma unroll 8
    for (int k = 0; k < Dd; ++k) {
        float a[4], bv[4];
#pragma unroll
        for (int m = 0; m < 4; ++m) a[m] = Qs[k][tr + m];
#pragma unroll
        for (int n = 0; n < 4; ++n) bv[n] = Ks[k][tc + n];
#pragma unroll
        for (int m = 0; m < 4; ++m)
#pragma unroll
            for (int n = 0; n < 4; ++n) acc[m][n] = fmaf(a[m], bv[n], acc[m][n]);
    }

    const float scale = 0.11785113019775793f;  // 1/sqrt(72)
    float* Sb = g_s + (size_t)bh * Nn * Nn;
#pragma unroll
    for (int m = 0; m < 4; ++m) {
        float4 o;
        o.x = acc[m][0] * scale;
        o.y = acc[m][1] * scale;
        o.z = acc[m][2] * scale;
        o.w = acc[m][3] * scale;
        *reinterpret_cast<float4*>(&Sb[(size_t)(m0 + tr + m) * Nn + n0 + tc]) = o;
    }
}

// ---------------------------------------------------------------------------
// Kernel 3: row softmax over 1024 elements. One 128-thread block per row,
// 8 values/thread held in registers, shuffle + smem reductions.
// ---------------------------------------------------------------------------
__global__ __launch_bounds__(128) void k_softmax() {
    const size_t base = (size_t)blockIdx.x * Nn;
    const int tid = threadIdx.x;
    __shared__ float red[4];

    float v[8];
    float mx = -3.4e38f;
#pragma unroll
    for (int i = 0; i < 8; ++i) {
        v[i] = g_s[base + tid + i * 128];
        mx = fmaxf(mx, v[i]);
    }
#pragma unroll
    for (int o = 16; o > 0; o >>= 1) mx = fmaxf(mx, __shfl_xor_sync(0xffffffffu, mx, o));
    if ((tid & 31) == 0) red[tid >> 5] = mx;
    __syncthreads();
    mx = fmaxf(fmaxf(red[0], red[1]), fmaxf(red[2], red[3]));
    __syncthreads();

    float sum = 0.f;
#pragma unroll
    for (int i = 0; i < 8; ++i) {
        v[i] = __expf(v[i] - mx);
        sum += v[i];
    }
#pragma unroll
    for (int o = 16; o > 0; o >>= 1) sum += __shfl_xor_sync(0xffffffffu, sum, o);
    if ((tid & 31) == 0) red[tid >> 5] = sum;
    __syncthreads();
    const float inv = 1.0f / (red[0] + red[1] + red[2] + red[3]);

#pragma unroll
    for (int i = 0; i < 8; ++i) g_s[base + tid + i * 128] = v[i] * inv;
}

// ---------------------------------------------------------------------------
// Kernel 4: O = P @ V per (b,h). [1024,1024]@[1024,72]. BM=128, BN=72 (full),
// BK=16; 32x8 thread grid with 4x9 microtiles. Epilogue writes [B,N,H*D].
// ---------------------------------------------------------------------------
__global__ __launch_bounds__(256) void k_pv() {
    constexpr int BM = 128, BK = 16;
    __shared__ float Ps[BK][BM];
    __shared__ float Vs[BK][Dd];

    const int bh = blockIdx.z;
    const int m0 = blockIdx.x * BM;
    const float* P = g_s + (size_t)bh * Nn * Nn;
    const float* V = g_v + (size_t)bh * Nn * Dd;
    const int tid = threadIdx.x;
    const int tr = (tid >> 3) * 4;   // 0..127 step 4
    const int tc = (tid & 7) * 9;    // 0..63 step 9

    float acc[4][9] = {};

    for (int k0 = 0; k0 < Nn; k0 += BK) {
#pragma unroll
        for (int l = 0; l < 2; ++l) {
            const int idx = tid + l * 256;          // 0..511 float4s
            const int r = idx >> 2;                 // 0..127
            const int c = (idx & 3) * 4;            // 0,4,8,12
            float4 p4 = *reinterpret_cast<const float4*>(&P[(size_t)(m0 + r) * Nn + k0 + c]);
            Ps[c + 0][r] = p4.x;
            Ps[c + 1][r] = p4.y;
            Ps[c + 2][r] = p4.z;
            Ps[c + 3][r] = p4.w;
        }
        for (int idx = tid; idx < BK * Dd; idx += 256) {
            const int r = idx / Dd;
            const int c = idx - r * Dd;
            Vs[r][c] = V[(size_t)(k0 + r) * Dd + c];
        }
        __syncthreads();
#pragma unroll
        for (int k = 0; k < BK; ++k) {
            float a[4], bv[9];
#pragma unroll
            for (int m = 0; m < 4; ++m) a[m] = Ps[k][tr + m];
#pragma unroll
            for (int n = 0; n < 9; ++n) bv[n] = Vs[k][tc + n];
#pragma unroll
            for (int m = 0; m < 4; ++m)
#pragma unroll
                for (int n = 0; n < 9; ++n) acc[m][n] = fmaf(a[m], bv[n], acc[m][n]);
        }
        __syncthreads();
    }

    const int b = bh >> 4;
    const int h = bh & 15;
#pragma unroll
    for (int m = 0; m < 4; ++m) {
        const int tok = m0 + tr + m;
        float* orow = g_o + ((size_t)(b * Nn + tok)) * HID + h * Dd + tc;
#pragma unroll
        for (int n = 0; n < 9; ++n) orow[n] = acc[m][n];
    }
}

// ---------------------------------------------------------------------------
// Kernel 5: out = g_o @ w_out + b_out. [4096,1152]@[1152,1152].
// Same structure as k_qkv, vectorized epilogue.
// ---------------------------------------------------------------------------
__global__ __launch_bounds__(256) void k_out(const float* __restrict__ W,
                                             const float* __restrict__ bias,
                                             float* __restrict__ C) {
    constexpr int BM = 128, BN = 128, BK = 8, TM = 8, TN = 8;
    __shared__ float As[BK][BM];
    __shared__ float Bs[BK][BN];

    const int tid  = threadIdx.x;
    const int row0 = blockIdx.y * BM;
    const int col0 = blockIdx.x * BN;
    const int arow = tid >> 1, acol = (tid & 1) * 4;
    const int brow = tid >> 5, bcol = (tid & 31) * 4;
    const int tr = (tid >> 4) * TM;
    const int tc = (tid & 15) * TN;

    float acc[TM][TN] = {};
    float ra[TM], rb[TN];

    for (int k0 = 0; k0 < HID; k0 += BK) {
        float4 a4 = *reinterpret_cast<const float4*>(&g_o[(size_t)(row0 + arow) * HID + k0 + acol]);
        As[acol + 0][arow] = a4.x;
        As[acol + 1][arow] = a4.y;
        As[acol + 2][arow] = a4.z;
        As[acol + 3][arow] = a4.w;
        float4 b4 = *reinterpret_cast<const float4*>(&W[(size_t)(k0 + brow) * HID + col0 + bcol]);
        *reinterpret_cast<float4*>(&Bs[brow][bcol]) = b4;
        __syncthreads();
#pragma unroll
        for (int k = 0; k < BK; ++k) {
#pragma unroll
            for (int m = 0; m < TM; ++m) ra[m] = As[k][tr + m];
#pragma unroll
            for (int n = 0; n < TN; ++n) rb[n] = Bs[k][tc + n];
#pragma unroll
            for (int m = 0; m < TM; ++m)
#pragma unroll
                for (int n = 0; n < TN; ++n) acc[m][n] = fmaf(ra[m], rb[n], acc[m][n]);
        }
        __syncthreads();
    }

#pragma unroll
    for (int m = 0; m < TM; ++m) {
        const size_t r = row0 + tr + m;
#pragma unroll
        for (int n = 0; n < TN; n += 4) {
            const int c = col0 + tc + n;
            float4 o;
            o.x = acc[m][n + 0] + bias[c + 0];
            o.y = acc[m][n + 1] + bias[c + 1];
            o.z = acc[m][n + 2] + bias[c + 2];
            o.w = acc[m][n + 3] + bias[c + 3];
            *reinterpret_cast<float4*>(&C[r * HID + c]) = o;
        }
    }
}

// ---------------------------------------------------------------------------
extern "C" void kernel_launch(void* const* d_in, const int* in_sizes, int n_in,
                              void* d_out, int out_size) {
    const float* x     = (const float*)d_in[0];
    const float* w_qkv = (const float*)d_in[1];
    const float* b_qkv = (const float*)d_in[2];
    const float* w_out = (const float*)d_in[3];
    const float* b_out = (const float*)d_in[4];
    float* out = (float*)d_out;

    // 1. QKV projection + scatter to [B,H,N,D]
    k_qkv<<<dim3(QKVN / 128, MTOK / 128), 256>>>(x, w_qkv, b_qkv);
    // 2. S = Q K^T * scale
    k_qkt<<<dim3(Nn / 64, Nn / 64, BHEAD), 256>>>();
    // 3. row softmax
    k_softmax<<<BHEAD * Nn, 128>>>();
    // 4. O = P @ V  -> [B,N,H*D]
    k_pv<<<dim3(Nn / 128, 1, BHEAD), 256>>>();
    // 5. output projection
    k_out<<<dim3(HID / 128, MTOK / 128), 256>>>(w_out, b_out, out);
}

// round 3
// speedup vs baseline: 1.5105x; 1.5105x over previous
#include <cuda_runtime.h>
#include <cuda_bf16.h>
#include <cstdint>

// ---------------------------------------------------------------------------
// Attention_21474836480706: B=4, N=1024, H=16, D=72, HID=1152 (fp32)
// R3: projections on mma.sync bf16 (hi/lo split, 3-pass = fp32-accurate),
// attention middle SIMT fp32. (tcgen05 unavailable: harness targets compute_100.)
// ---------------------------------------------------------------------------

namespace {
constexpr int Bb    = 4;
constexpr int Nn    = 1024;
constexpr int Hh    = 16;
constexpr int Dd    = 72;
constexpr int HID   = 1152;
constexpr int ATT   = Hh * Dd;        // 1152
constexpr int MTOK  = Bb * Nn;        // 4096
constexpr int QKVN  = 3 * ATT;        // 3456
constexpr int BHEAD = Bb * Hh;        // 64
}

// ------------------------------ scratch ------------------------------------
__device__ float g_q[(size_t)BHEAD * Nn * Dd];
__device__ float g_k[(size_t)BHEAD * Nn * Dd];
__device__ float g_v[(size_t)BHEAD * Nn * Dd];
__device__ float g_s[(size_t)BHEAD * Nn * Nn];      // 256 MB S/P

__device__ __align__(16) __nv_bfloat16 g_xa_hi[(size_t)MTOK * HID];
__device__ __align__(16) __nv_bfloat16 g_xa_lo[(size_t)MTOK * HID];
__device__ __align__(16) __nv_bfloat16 g_oa_hi[(size_t)MTOK * HID];   // attn out, hi
__device__ __align__(16) __nv_bfloat16 g_oa_lo[(size_t)MTOK * HID];   // attn out, lo
__device__ __align__(16) __nv_bfloat16 g_wqkvt_hi[(size_t)QKVN * HID]; // [3456][1152] k-major
__device__ __align__(16) __nv_bfloat16 g_wqkvt_lo[(size_t)QKVN * HID];
__device__ __align__(16) __nv_bfloat16 g_wot_hi[(size_t)HID * HID];    // [1152][1152] k-major
__device__ __align__(16) __nv_bfloat16 g_wot_lo[(size_t)HID * HID];

// --------------------------- mma helper ------------------------------------
__device__ __forceinline__ void mma16816(float* d, const uint32_t* a, const uint32_t* b) {
    asm volatile(
        "mma.sync.aligned.m16n8k16.row.col.f32.bf16.bf16.f32 "
        "{%0,%1,%2,%3}, {%4,%5,%6,%7}, {%8,%9}, {%0,%1,%2,%3};"
        : "+f"(d[0]), "+f"(d[1]), "+f"(d[2]), "+f"(d[3])
        : "r"(a[0]), "r"(a[1]), "r"(a[2]), "r"(a[3]), "r"(b[0]), "r"(b[1]));
}

// ---------------------------------------------------------------------------
// split: x fp32 -> bf16 hi + lo
// ---------------------------------------------------------------------------
__global__ __launch_bounds__(256) void k_split(const float* __restrict__ in) {
    const int n4 = MTOK * HID / 4;
    int i = blockIdx.x * 256 + threadIdx.x;
    if (i >= n4) return;
    float4 v = reinterpret_cast<const float4*>(in)[i];
    __nv_bfloat16 h0 = __float2bfloat16(v.x), h1 = __float2bfloat16(v.y);
    __nv_bfloat16 h2 = __float2bfloat16(v.z), h3 = __float2bfloat16(v.w);
    __nv_bfloat16 l0 = __float2bfloat16(v.x - __bfloat162float(h0));
    __nv_bfloat16 l1 = __float2bfloat16(v.y - __bfloat162float(h1));
    __nv_bfloat16 l2 = __float2bfloat16(v.z - __bfloat162float(h2));
    __nv_bfloat16 l3 = __float2bfloat16(v.w - __bfloat162float(h3));
    reinterpret_cast<__nv_bfloat162*>(g_xa_hi)[2 * i]     = __halves2bfloat162(h0, h1);
    reinterpret_cast<__nv_bfloat162*>(g_xa_hi)[2 * i + 1] = __halves2bfloat162(h2, h3);
    reinterpret_cast<__nv_bfloat162*>(g_xa_lo)[2 * i]     = __halves2bfloat162(l0, l1);
    reinterpret_cast<__nv_bfloat162*>(g_xa_lo)[2 * i + 1] = __halves2bfloat162(l2, l3);
}

// ---------------------------------------------------------------------------
// transpose + split: W[K=1152][NCOLS] fp32 -> Wt hi/lo [NCOLS][1152] bf16
// ---------------------------------------------------------------------------
template <int NCOLS, int WHICH>
__global__ void k_tsplit(const float* __restrict__ W) {
    __shared__ float t[32][33];
    const int n0 = blockIdx.x * 32, k0 = blockIdx.y * 32;
    const int tx = threadIdx.x, ty = threadIdx.y;   // (32, 8)
#pragma unroll
    for (int i = 0; i < 4; ++i)
        t[ty * 4 + i][tx] = W[(size_t)(k0 + ty * 4 + i) * NCOLS + n0 + tx];
    __syncthreads();
    __nv_bfloat16* Hi = WHICH ? g_wot_hi : g_wqkvt_hi;
    __nv_bfloat16* Lo = WHICH ? g_wot_lo : g_wqkvt_lo;
#pragma unroll
    for (int i = 0; i < 4; ++i) {
        float v = t[tx][ty * 4 + i];
        __nv_bfloat16 h = __float2bfloat16(v);
        __nv_bfloat16 l = __float2bfloat16(v - __bfloat162float(h));
        size_t o = (size_t)(n0 + ty * 4 + i) * HID + k0 + tx;
        Hi[o] = h;
        Lo[o] = l;
    }
}

// ---------------------------------------------------------------------------
// HMMA GEMM: C[128x128] = A[M,1152] * B^T (B stored [N,1152] k-major), hi/lo.
// MODE=0: A=g_xa, B=g_wqkvt -> scatter Q/K/V (+b_qkv)
// MODE=1: A=g_oa, B=g_wot   -> Cout (+b_out)
// 8 warps (2m x 4n), warp tile 64x32, BK=32, smem row stride 40 (conflict-free
// fragment loads: bank = row*20 + lane%4 covers all 32 banks).
// ---------------------------------------------------------------------------
template <int MODE>
__global__ __launch_bounds__(256) void k_gemm(const float* __restrict__ bias,
                                              float* __restrict__ Cout) {
    constexpr int BM = 128, BN = 128, BK = 32, LDS = 40;
    __shared__ __align__(16) __nv_bfloat16 sAh[BM * LDS];
    __shared__ __align__(16) __nv_bfloat16 sAl[BM * LDS];
    __shared__ __align__(16) __nv_bfloat16 sBh[BN * LDS];
    __shared__ __align__(16) __nv_bfloat16 sBl[BN * LDS];

    const int tid  = threadIdx.x;
    const int warp = tid >> 5, lane = tid & 31;
    const int wm = (warp >> 2) * 64;      // 0,64
    const int wn = (warp & 3) * 32;       // 0,32,64,96
    const int g   = lane >> 2;            // 0..7
    const int tig = lane & 3;             // 0..3
    const int m0 = blockIdx.y * BM;
    const int n0 = blockIdx.x * BN;

    const __nv_bfloat16* __restrict__ Ah = MODE ? g_oa_hi : g_xa_hi;
    const __nv_bfloat16* __restrict__ Al = MODE ? g_oa_lo : g_xa_lo;
    const __nv_bfloat16* __restrict__ Bh = MODE ? g_wot_hi : g_wqkvt_hi;
    const __nv_bfloat16* __restrict__ Bl = MODE ? g_wot_lo : g_wqkvt_lo;

    float acc[4][4][4] = {};   // [mf][nf][reg]

    for (int k0 = 0; k0 < HID; k0 += BK) {
        if (k0) __syncthreads();
#pragma unroll
        for (int c = 0; c < 2; ++c) {
            const int chunk = tid + c * 256;      // 0..511
            const int row = chunk >> 2;           // 0..127
            const int kc  = chunk & 3;            // 0..3 (8-elem units)
            const int soff = row * LDS + kc * 8;
            const size_t ga = (size_t)(m0 + row) * HID + k0 + kc * 8;
            const size_t gb = (size_t)(n0 + row) * HID + k0 + kc * 8;
            *reinterpret_cast<uint4*>(&sAh[soff]) = *reinterpret_cast<const uint4*>(&Ah[ga]);
            *reinterpret_cast<uint4*>(&sAl[soff]) = *reinterpret_cast<const uint4*>(&Al[ga]);
            *reinterpret_cast<uint4*>(&sBh[soff]) = *reinterpret_cast<const uint4*>(&Bh[gb]);
            *reinterpret_cast<uint4*>(&sBl[soff]) = *reinterpret_cast<const uint4*>(&Bl[gb]);
        }
        __syncthreads();

#pragma unroll
        for (int ks = 0; ks < BK; ks += 16) {
            uint32_t ah[4][4], al[4][4], b[4][2];
            // A fragments (hi and lo)
#pragma unroll
            for (int mf = 0; mf < 4; ++mf) {
                const int r0 = (wm + mf * 16 + g) * LDS + ks + tig * 2;
                const int r1 = r0 + 8 * LDS;
                ah[mf][0] = *reinterpret_cast<const uint32_t*>(&sAh[r0]);
                ah[mf][1] = *reinterpret_cast<const uint32_t*>(&sAh[r1]);
                ah[mf][2] = *reinterpret_cast<const uint32_t*>(&sAh[r0 + 8]);
                ah[mf][3] = *reinterpret_cast<const uint32_t*>(&sAh[r1 + 8]);
                al[mf][0] = *reinterpret_cast<const uint32_t*>(&sAl[r0]);
                al[mf][1] = *reinterpret_cast<const uint32_t*>(&sAl[r1]);
                al[mf][2] = *reinterpret_cast<const uint32_t*>(&sAl[r0 + 8]);
                al[mf][3] = *reinterpret_cast<const uint32_t*>(&sAl[r1 + 8]);
            }
            // B hi fragments: pass hi*hi and lo*hi
#pragma unroll
            for (int nf = 0; nf < 4; ++nf) {
                const int r = (wn + nf * 8 + g) * LDS + ks + tig * 2;
                b[nf][0] = *reinterpret_cast<const uint32_t*>(&sBh[r]);
                b[nf][1] = *reinterpret_cast<const uint32_t*>(&sBh[r + 8]);
            }
#pragma unroll
            for (int mf = 0; mf < 4; ++mf)
#pragma unroll
                for (int nf = 0; nf < 4; ++nf) {
                    mma16816(acc[mf][nf], ah[mf], b[nf]);
                    mma16816(acc[mf][nf], al[mf], b[nf]);
                }
            // B lo fragments: pass hi*lo
#pragma unroll
            for (int nf = 0; nf < 4; ++nf) {
                const int r = (wn + nf * 8 + g) * LDS + ks + tig * 2;
                b[nf][0] = *reinterpret_cast<const uint32_t*>(&sBl[r]);
                b[nf][1] = *reinterpret_cast<const uint32_t*>(&sBl[r + 8]);
            }
#pragma unroll
            for (int mf = 0; mf < 4; ++mf)
#pragma unroll
                for (int nf = 0; nf < 4; ++nf)
                    mma16816(acc[mf][nf], ah[mf], b[nf]);
        }
    }

    // epilogue
#pragma unroll
    for (int mf = 0; mf < 4; ++mf) {
#pragma unroll
        for (int nf = 0; nf < 4; ++nf) {
            const int row = m0 + wm + mf * 16 + g;
            const int col = n0 + wn + nf * 8 + tig * 2;
            const float b0 = bias[col], b1 = bias[col + 1];
            float2 v0 = make_float2(acc[mf][nf][0] + b0, acc[mf][nf][1] + b1);
            float2 v1 = make_float2(acc[mf][nf][2] + b0, acc[mf][nf][3] + b1);
            if (MODE == 0) {
                const int which = n0 / ATT;
                float* dst = (which == 0) ? g_q : (which == 1) ? g_k : g_v;
                const int rem = col - which * ATT;
                const int h = rem / Dd, d = rem - h * Dd;
                const int bb = row >> 10, tok = row & 1023;
                const size_t base = ((size_t)(bb * Hh + h) * Nn);
                *reinterpret_cast<float2*>(&dst[(base + tok) * Dd + d])     = v0;
                *reinterpret_cast<float2*>(&dst[(base + tok + 8) * Dd + d]) = v1;
            } else {
                *reinterpret_cast<float2*>(&Cout[(size_t)row * HID + col])       = v0;
                *reinterpret_cast<float2*>(&Cout[(size_t)(row + 8) * HID + col]) = v1;
            }
        }
    }
}

// ---------------------------------------------------------------------------
// Attention middle (SIMT fp32)
// ---------------------------------------------------------------------------
__global__ __launch_bounds__(256) void k_qkt() {
    constexpr int BM = 64, BN = 64;
    __shared__ float Qs[Dd][BM];
    __shared__ float Ks[Dd][BN];

    const int bh = blockIdx.z;
    const float* Q = g_q + (size_t)bh * Nn * Dd;
    const float* K = g_k + (size_t)bh * Nn * Dd;
    const int m0 = blockIdx.y * BM;
    const int n0 = blockIdx.x * BN;
    const int tid = threadIdx.x;

    for (int idx = tid; idx < BM * Dd; idx += 256) {
        const int r = idx / Dd;
        const int c = idx - r * Dd;
        Qs[c][r] = Q[(size_t)(m0 + r) * Dd + c];
        Ks[c][r] = K[(size_t)(n0 + r) * Dd + c];
    }
    __syncthreads();

    const int tr = (tid >> 4) * 4;
    const int tc = (tid & 15) * 4;
    float acc[4][4] = {};
#pragma unroll 8
    for (int k = 0; k < Dd; ++k) {
        float a[4], bv[4];
#pragma unroll
        for (int m = 0; m < 4; ++m) a[m] = Qs[k][tr + m];
#pragma unroll
        for (int n = 0; n < 4; ++n) bv[n] = Ks[k][tc + n];
#pragma unroll
        for (int m = 0; m < 4; ++m)
#pragma unroll
            for (int n = 0; n < 4; ++n) acc[m][n] = fmaf(a[m], bv[n], acc[m][n]);
    }

    const float scale = 0.11785113019775793f;  // 1/sqrt(72)
    float* Sb = g_s + (size_t)bh * Nn * Nn;
#pragma unroll
    for (int m = 0; m < 4; ++m) {
        float4 o;
        o.x = acc[m][0] * scale;
        o.y = acc[m][1] * scale;
        o.z = acc[m][2] * scale;
        o.w = acc[m][3] * scale;
        *reinterpret_cast<float4*>(&Sb[(size_t)(m0 + tr + m) * Nn + n0 + tc]) = o;
    }
}

__global__ __launch_bounds__(128) void k_softmax() {
    const size_t base = (size_t)blockIdx.x * Nn;
    const int tid = threadIdx.x;
    __shared__ float red[4];

    float v[8];
    float mx = -3.4e38f;
#pragma unroll
    for (int i = 0; i < 8; ++i) {
        v[i] = g_s[base + tid + i * 128];
        mx = fmaxf(mx, v[i]);
    }
#pragma unroll
    for (int o = 16; o > 0; o >>= 1) mx = fmaxf(mx, __shfl_xor_sync(0xffffffffu, mx, o));
    if ((tid & 31) == 0) red[tid >> 5] = mx;
    __syncthreads();
    mx = fmaxf(fmaxf(red[0], red[1]), fmaxf(red[2], red[3]));
    __syncthreads();

    float sum = 0.f;
#pragma unroll
    for (int i = 0; i < 8; ++i) {
        v[i] = __expf(v[i] - mx);
        sum += v[i];
    }
#pragma unroll
    for (int o = 16; o > 0; o >>= 1) sum += __shfl_xor_sync(0xffffffffu, sum, o);
    if ((tid & 31) == 0) red[tid >> 5] = sum;
    __syncthreads();
    const float inv = 1.0f / (red[0] + red[1] + red[2] + red[3]);

#pragma unroll
    for (int i = 0; i < 8; ++i) g_s[base + tid + i * 128] = v[i] * inv;
}

// O = P @ V per (b,h); epilogue writes hi/lo bf16 directly (fused split).
__global__ __launch_bounds__(256) void k_pv() {
    constexpr int BM = 128, BK = 16;
    __shared__ float Ps[BK][BM];
    __shared__ float Vs[BK][Dd];

    const int bh = blockIdx.z;
    const int m0 = blockIdx.x * BM;
    const float* P = g_s + (size_t)bh * Nn * Nn;
    const float* V = g_v + (size_t)bh * Nn * Dd;
    const int tid = threadIdx.x;
    const int tr = (tid >> 3) * 4;
    const int tc = (tid & 7) * 9;

    float acc[4][9] = {};

    for (int k0 = 0; k0 < Nn; k0 += BK) {
#pragma unroll
        for (int l = 0; l < 2; ++l) {
            const int idx = tid + l * 256;
            const int r = idx >> 2;
            const int c = (idx & 3) * 4;
            float4 p4 = *reinterpret_cast<const float4*>(&P[(size_t)(m0 + r) * Nn + k0 + c]);
            Ps[c + 0][r] = p4.x;
            Ps[c + 1][r] = p4.y;
            Ps[c + 2][r] = p4.z;
            Ps[c + 3][r] = p4.w;
        }
        for (int idx = tid; idx < BK * Dd; idx += 256) {
            const int r = idx / Dd;
            const int c = idx - r * Dd;
            Vs[r][c] = V[(size_t)(k0 + r) * Dd + c];
        }
        __syncthreads();
#pragma unroll
        for (int k = 0; k < BK; ++k) {
            float a[4], bv[9];
#pragma unroll
            for (int m = 0; m < 4; ++m) a[m] = Ps[k][tr + m];
#pragma unroll
            for (int n = 0; n < 9; ++n) bv[n] = Vs[k][tc + n];
#pragma unroll
            for (int m = 0; m < 4; ++m)
#pragma unroll
                for (int n = 0; n < 9; ++n) acc[m][n] = fmaf(a[m], bv[n], acc[m][n]);
        }
        __syncthreads();
    }

    const int b = bh >> 4;
    const int h = bh & 15;
#pragma unroll
    for (int m = 0; m < 4; ++m) {
        const int tok = m0 + tr + m;
        const size_t o = ((size_t)(b * Nn + tok)) * HID + h * Dd + tc;
#pragma unroll
        for (int n = 0; n < 9; ++n) {
            const float v = acc[m][n];
            const __nv_bfloat16 hi = __float2bfloat16(v);
            g_oa_hi[o + n] = hi;
            g_oa_lo[o + n] = __float2bfloat16(v - __bfloat162float(hi));
        }
    }
}

// ---------------------------------------------------------------------------
extern "C" void kernel_launch(void* const* d_in, const int* in_sizes, int n_in,
                              void* d_out, int out_size) {
    const float* x     = (const float*)d_in[0];
    const float* w_qkv = (const float*)d_in[1];
    const float* b_qkv = (const float*)d_in[2];
    const float* w_out = (const float*)d_in[3];
    const float* b_out = (const float*)d_in[4];
    float* out = (float*)d_out;

    const int n4 = MTOK * HID / 4;

    // operand prep
    k_split<<<(n4 + 255) / 256, 256>>>(x);
    k_tsplit<QKVN, 0><<<dim3(QKVN / 32, HID / 32), dim3(32, 8)>>>(w_qkv);
    k_tsplit<HID, 1><<<dim3(HID / 32, HID / 32), dim3(32, 8)>>>(w_out);

    // 1. QKV projection (HMMA) -> g_q/g_k/g_v
    k_gemm<0><<<dim3(QKVN / 128, MTOK / 128), 256>>>(b_qkv, nullptr);

    // 2-4. attention middle
    k_qkt<<<dim3(Nn / 64, Nn / 64, BHEAD), 256>>>();
    k_softmax<<<BHEAD * Nn, 128>>>();
    k_pv<<<dim3(Nn / 128, 1, BHEAD), 256>>>();

    // 5. output projection (HMMA)
    k_gemm<1><<<dim3(HID / 128, MTOK / 128), 256>>>(b_out, out);
}

// round 4
// speedup vs baseline: 2.9780x; 1.9715x over previous
#include <cuda_runtime.h>
#include <cuda_bf16.h>
#include <cstdint>

// ---------------------------------------------------------------------------
// Attention_21474836480706: B=4, N=1024, H=16, D=72, HID=1152 (fp32)
// R4: ALL GEMMs (qkv proj, QK^T, PV, out proj) on mma.sync bf16 hi/lo 3-pass.
// ---------------------------------------------------------------------------

namespace {
constexpr int Bb    = 4;
constexpr int Nn    = 1024;
constexpr int Hh    = 16;
constexpr int Dd    = 72;
constexpr int DP    = 80;             // D padded to mult of 16
constexpr int HID   = 1152;
constexpr int ATT   = Hh * Dd;        // 1152
constexpr int MTOK  = Bb * Nn;        // 4096
constexpr int QKVN  = 3 * ATT;        // 3456
constexpr int BHEAD = Bb * Hh;        // 64
}

// ------------------------------ scratch ------------------------------------
__device__ float g_s[(size_t)BHEAD * Nn * Nn];                          // S fp32
__device__ __align__(16) __nv_bfloat16 g_ph[(size_t)BHEAD * Nn * Nn];   // P hi
__device__ __align__(16) __nv_bfloat16 g_pl[(size_t)BHEAD * Nn * Nn];   // P lo

__device__ __align__(16) __nv_bfloat16 g_qh[(size_t)BHEAD * Nn * DP];
__device__ __align__(16) __nv_bfloat16 g_ql[(size_t)BHEAD * Nn * DP];
__device__ __align__(16) __nv_bfloat16 g_kh[(size_t)BHEAD * Nn * DP];
__device__ __align__(16) __nv_bfloat16 g_kl[(size_t)BHEAD * Nn * DP];
__device__ __align__(16) __nv_bfloat16 g_vth[(size_t)BHEAD * Dd * Nn];  // V^T [bh][d][tok]
__device__ __align__(16) __nv_bfloat16 g_vtl[(size_t)BHEAD * Dd * Nn];

__device__ __align__(16) __nv_bfloat16 g_xa_hi[(size_t)MTOK * HID];
__device__ __align__(16) __nv_bfloat16 g_xa_lo[(size_t)MTOK * HID];
__device__ __align__(16) __nv_bfloat16 g_oa_hi[(size_t)MTOK * HID];
__device__ __align__(16) __nv_bfloat16 g_oa_lo[(size_t)MTOK * HID];
__device__ __align__(16) __nv_bfloat16 g_wqkvt_hi[(size_t)QKVN * HID];
__device__ __align__(16) __nv_bfloat16 g_wqkvt_lo[(size_t)QKVN * HID];
__device__ __align__(16) __nv_bfloat16 g_wot_hi[(size_t)HID * HID];
__device__ __align__(16) __nv_bfloat16 g_wot_lo[(size_t)HID * HID];

// --------------------------- mma helper ------------------------------------
__device__ __forceinline__ void mma16816(float* d, const uint32_t* a, const uint32_t* b) {
    asm volatile(
        "mma.sync.aligned.m16n8k16.row.col.f32.bf16.bf16.f32 "
        "{%0,%1,%2,%3}, {%4,%5,%6,%7}, {%8,%9}, {%0,%1,%2,%3};"
        : "+f"(d[0]), "+f"(d[1]), "+f"(d[2]), "+f"(d[3])
        : "r"(a[0]), "r"(a[1]), "r"(a[2]), "r"(a[3]), "r"(b[0]), "r"(b[1]));
}
__device__ __forceinline__ __nv_bfloat162 hilo2(float a, float b, bool lo) {
    __nv_bfloat16 ha = __float2bfloat16(a), hb = __float2bfloat16(b);
    if (!lo) return __halves2bfloat162(ha, hb);
    return __halves2bfloat162(__float2bfloat16(a - __bfloat162float(ha)),
                              __float2bfloat16(b - __bfloat162float(hb)));
}

// ---------------------------------------------------------------------------
// zero D-padding columns (72..79) of Q/K hi/lo
// ---------------------------------------------------------------------------
__global__ __launch_bounds__(256) void k_zpad() {
    const int i = blockIdx.x * 256 + threadIdx.x;
    if (i >= BHEAD * Nn) return;
    const size_t o = (size_t)i * DP + Dd;
    const uint4 z = make_uint4(0, 0, 0, 0);
    *reinterpret_cast<uint4*>(&g_qh[o]) = z;
    *reinterpret_cast<uint4*>(&g_ql[o]) = z;
    *reinterpret_cast<uint4*>(&g_kh[o]) = z;
    *reinterpret_cast<uint4*>(&g_kl[o]) = z;
}

// ---------------------------------------------------------------------------
// split x fp32 -> bf16 hi+lo
// ---------------------------------------------------------------------------
__global__ __launch_bounds__(256) void k_split(const float* __restrict__ in) {
    const int n4 = MTOK * HID / 4;
    int i = blockIdx.x * 256 + threadIdx.x;
    if (i >= n4) return;
    float4 v = reinterpret_cast<const float4*>(in)[i];
    reinterpret_cast<__nv_bfloat162*>(g_xa_hi)[2 * i]     = hilo2(v.x, v.y, false);
    reinterpret_cast<__nv_bfloat162*>(g_xa_hi)[2 * i + 1] = hilo2(v.z, v.w, false);
    reinterpret_cast<__nv_bfloat162*>(g_xa_lo)[2 * i]     = hilo2(v.x, v.y, true);
    reinterpret_cast<__nv_bfloat162*>(g_xa_lo)[2 * i + 1] = hilo2(v.z, v.w, true);
}

// ---------------------------------------------------------------------------
// transpose + split: W[K][NCOLS] fp32 -> Wt hi/lo [NCOLS][K=1152] bf16
// ---------------------------------------------------------------------------
template <int NCOLS, int WHICH>
__global__ void k_tsplit(const float* __restrict__ W) {
    __shared__ float t[32][33];
    const int n0 = blockIdx.x * 32, k0 = blockIdx.y * 32;
    const int tx = threadIdx.x, ty = threadIdx.y;   // (32, 8)
#pragma unroll
    for (int i = 0; i < 4; ++i)
        t[ty * 4 + i][tx] = W[(size_t)(k0 + ty * 4 + i) * NCOLS + n0 + tx];
    __syncthreads();
    __nv_bfloat16* Hi = WHICH ? g_wot_hi : g_wqkvt_hi;
    __nv_bfloat16* Lo = WHICH ? g_wot_lo : g_wqkvt_lo;
#pragma unroll
    for (int i = 0; i < 4; ++i) {
        float v = t[tx][ty * 4 + i];
        __nv_bfloat16 h = __float2bfloat16(v);
        __nv_bfloat16 l = __float2bfloat16(v - __bfloat162float(h));
        size_t o = (size_t)(n0 + ty * 4 + i) * HID + k0 + tx;
        Hi[o] = h;
        Lo[o] = l;
    }
}

// ---------------------------------------------------------------------------
// HMMA GEMM (projections): C[128x128] = A[M,1152]*B^T, hi/lo 3-pass.
// MODE=0: scatter Q/K hi/lo (D-pad layout) + V^T hi/lo, +b_qkv
// MODE=1: Cout = +b_out
// ---------------------------------------------------------------------------
template <int MODE>
__global__ __launch_bounds__(256) void k_gemm(const float* __restrict__ bias,
                                              float* __restrict__ Cout) {
    constexpr int BM = 128, BN = 128, BK = 32, LDS = 40;
    __shared__ __align__(16) __nv_bfloat16 sAh[BM * LDS];
    __shared__ __align__(16) __nv_bfloat16 sAl[BM * LDS];
    __shared__ __align__(16) __nv_bfloat16 sBh[BN * LDS];
    __shared__ __align__(16) __nv_bfloat16 sBl[BN * LDS];

    const int tid  = threadIdx.x;
    const int warp = tid >> 5, lane = tid & 31;
    const int wm = (warp >> 2) * 64;
    const int wn = (warp & 3) * 32;
    const int gi  = lane >> 2;
    const int tig = lane & 3;
    const int m0 = blockIdx.y * BM;
    const int n0 = blockIdx.x * BN;

    const __nv_bfloat16* __restrict__ Ah = MODE ? g_oa_hi : g_xa_hi;
    const __nv_bfloat16* __restrict__ Al = MODE ? g_oa_lo : g_xa_lo;
    const __nv_bfloat16* __restrict__ Bh = MODE ? g_wot_hi : g_wqkvt_hi;
    const __nv_bfloat16* __restrict__ Bl = MODE ? g_wot_lo : g_wqkvt_lo;

    float acc[4][4][4] = {};

    for (int k0 = 0; k0 < HID; k0 += BK) {
        if (k0) __syncthreads();
#pragma unroll
        for (int c = 0; c < 2; ++c) {
            const int chunk = tid + c * 256;
            const int row = chunk >> 2;
            const int kc  = chunk & 3;
            const int soff = row * LDS + kc * 8;
            const size_t ga = (size_t)(m0 + row) * HID + k0 + kc * 8;
            const size_t gb = (size_t)(n0 + row) * HID + k0 + kc * 8;
            *reinterpret_cast<uint4*>(&sAh[soff]) = *reinterpret_cast<const uint4*>(&Ah[ga]);
            *reinterpret_cast<uint4*>(&sAl[soff]) = *reinterpret_cast<const uint4*>(&Al[ga]);
            *reinterpret_cast<uint4*>(&sBh[soff]) = *reinterpret_cast<const uint4*>(&Bh[gb]);
            *reinterpret_cast<uint4*>(&sBl[soff]) = *reinterpret_cast<const uint4*>(&Bl[gb]);
        }
        __syncthreads();

#pragma unroll
        for (int ks = 0; ks < BK; ks += 16) {
            uint32_t ah[4][4], al[4][4], b[4][2];
#pragma unroll
            for (int mf = 0; mf < 4; ++mf) {
                const int r0 = (wm + mf * 16 + gi) * LDS + ks + tig * 2;
                const int r1 = r0 + 8 * LDS;
                ah[mf][0] = *reinterpret_cast<const uint32_t*>(&sAh[r0]);
                ah[mf][1] = *reinterpret_cast<const uint32_t*>(&sAh[r1]);
                ah[mf][2] = *reinterpret_cast<const uint32_t*>(&sAh[r0 + 8]);
                ah[mf][3] = *reinterpret_cast<const uint32_t*>(&sAh[r1 + 8]);
                al[mf][0] = *reinterpret_cast<const uint32_t*>(&sAl[r0]);
                al[mf][1] = *reinterpret_cast<const uint32_t*>(&sAl[r1]);
                al[mf][2] = *reinterpret_cast<const uint32_t*>(&sAl[r0 + 8]);
                al[mf][3] = *reinterpret_cast<const uint32_t*>(&sAl[r1 + 8]);
            }
#pragma unroll
            for (int nf = 0; nf < 4; ++nf) {
                const int r = (wn + nf * 8 + gi) * LDS + ks + tig * 2;
                b[nf][0] = *reinterpret_cast<const uint32_t*>(&sBh[r]);
                b[nf][1] = *reinterpret_cast<const uint32_t*>(&sBh[r + 8]);
            }
#pragma unroll
            for (int mf = 0; mf < 4; ++mf)
#pragma unroll
                for (int nf = 0; nf < 4; ++nf) {
                    mma16816(acc[mf][nf], ah[mf], b[nf]);
                    mma16816(acc[mf][nf], al[mf], b[nf]);
                }
#pragma unroll
            for (int nf = 0; nf < 4; ++nf) {
                const int r = (wn + nf * 8 + gi) * LDS + ks + tig * 2;
                b[nf][0] = *reinterpret_cast<const uint32_t*>(&sBl[r]);
                b[nf][1] = *reinterpret_cast<const uint32_t*>(&sBl[r + 8]);
            }
#pragma unroll
            for (int mf = 0; mf < 4; ++mf)
#pragma unroll
                for (int nf = 0; nf < 4; ++nf)
                    mma16816(acc[mf][nf], ah[mf], b[nf]);
        }
    }

#pragma unroll
    for (int mf = 0; mf < 4; ++mf) {
#pragma unroll
        for (int nf = 0; nf < 4; ++nf) {
            const int row = m0 + wm + mf * 16 + gi;
            const int col = n0 + wn + nf * 8 + tig * 2;
            const float b0 = bias[col], b1 = bias[col + 1];
            const float x0 = acc[mf][nf][0] + b0, y0 = acc[mf][nf][1] + b1;
            const float x1 = acc[mf][nf][2] + b0, y1 = acc[mf][nf][3] + b1;
            if (MODE == 0) {
                const int which = n0 / ATT;
                const int rem = col - which * ATT;
                const int h = rem / Dd, d = rem - h * Dd;
                const int bb = row >> 10, tok = row & 1023;
                const int bh = bb * Hh + h;
                if (which < 2) {
                    __nv_bfloat16* Hi = which ? g_kh : g_qh;
                    __nv_bfloat16* Lo = which ? g_kl : g_ql;
                    const size_t o0 = ((size_t)bh * Nn + tok) * DP + d;
                    const size_t o1 = o0 + 8 * DP;
                    *reinterpret_cast<__nv_bfloat162*>(&Hi[o0]) = hilo2(x0, y0, false);
                    *reinterpret_cast<__nv_bfloat162*>(&Lo[o0]) = hilo2(x0, y0, true);
                    *reinterpret_cast<__nv_bfloat162*>(&Hi[o1]) = hilo2(x1, y1, false);
                    *reinterpret_cast<__nv_bfloat162*>(&Lo[o1]) = hilo2(x1, y1, true);
                } else {
                    // V transposed: [bh][d][tok]
                    const size_t b0o = ((size_t)bh * Dd + d) * Nn + tok;
                    const size_t b1o = b0o + Nn;   // d+1
                    __nv_bfloat16 h0 = __float2bfloat16(x0);
                    __nv_bfloat16 h1 = __float2bfloat16(y0);
                    __nv_bfloat16 h2 = __float2bfloat16(x1);
                    __nv_bfloat16 h3 = __float2bfloat16(y1);
                    g_vth[b0o]     = h0;
                    g_vth[b1o]     = h1;
                    g_vth[b0o + 8] = h2;
                    g_vth[b1o + 8] = h3;
                    g_vtl[b0o]     = __float2bfloat16(x0 - __bfloat162float(h0));
                    g_vtl[b1o]     = __float2bfloat16(y0 - __bfloat162float(h1));
                    g_vtl[b0o + 8] = __float2bfloat16(x1 - __bfloat162float(h2));
                    g_vtl[b1o + 8] = __float2bfloat16(y1 - __bfloat162float(h3));
                }
            } else {
                *reinterpret_cast<float2*>(&Cout[(size_t)row * HID + col]) = make_float2(x0, y0);
                *reinterpret_cast<float2*>(&Cout[(size_t)(row + 8) * HID + col]) = make_float2(x1, y1);
            }
        }
    }
}

// ---------------------------------------------------------------------------
// QK^T on HMMA: S[128x128 tile] per (b,h). Full K=80 in smem, stride 88.
// ---------------------------------------------------------------------------
__global__ __launch_bounds__(256) void k_qkt_tc() {
    constexpr int LDS = 88, TSZ = 128 * LDS;
    extern __shared__ __nv_bfloat16 sm[];
    __nv_bfloat16* sQh = sm;
    __nv_bfloat16* sQl = sm + TSZ;
    __nv_bfloat16* sKh = sm + 2 * TSZ;
    __nv_bfloat16* sKl = sm + 3 * TSZ;

    const int tid  = threadIdx.x;
    const int warp = tid >> 5, lane = tid & 31;
    const int wm = (warp >> 2) * 64;
    const int wn = (warp & 3) * 32;
    const int gi  = lane >> 2;
    const int tig = lane & 3;
    const int bh = blockIdx.z;
    const int m0 = blockIdx.y * 128;
    const int n0 = blockIdx.x * 128;

    const __nv_bfloat16* __restrict__ Qh = g_qh + (size_t)bh * Nn * DP;
    const __nv_bfloat16* __restrict__ Ql = g_ql + (size_t)bh * Nn * DP;
    const __nv_bfloat16* __restrict__ Kh = g_kh + (size_t)bh * Nn * DP;
    const __nv_bfloat16* __restrict__ Kl = g_kl + (size_t)bh * Nn * DP;

#pragma unroll
    for (int c = 0; c < 5; ++c) {
        const int chunk = tid + c * 256;        // 0..1279
        const int row = chunk / 10;
        const int kc  = chunk - row * 10;       // 0..9
        const int soff = row * LDS + kc * 8;
        const size_t gq = (size_t)(m0 + row) * DP + kc * 8;
        const size_t gk = (size_t)(n0 + row) * DP + kc * 8;
        *reinterpret_cast<uint4*>(&sQh[soff]) = *reinterpret_cast<const uint4*>(&Qh[gq]);
        *reinterpret_cast<uint4*>(&sQl[soff]) = *reinterpret_cast<const uint4*>(&Ql[gq]);
        *reinterpret_cast<uint4*>(&sKh[soff]) = *reinterpret_cast<const uint4*>(&Kh[gk]);
        *reinterpret_cast<uint4*>(&sKl[soff]) = *reinterpret_cast<const uint4*>(&Kl[gk]);
    }
    __syncthreads();

    float acc[4][4][4] = {};
#pragma unroll
    for (int ks = 0; ks < DP; ks += 16) {
        uint32_t ah[4][4], al[4][4], b[4][2];
#pragma unroll
        for (int mf = 0; mf < 4; ++mf) {
            const int r0 = (wm + mf * 16 + gi) * LDS + ks + tig * 2;
            const int r1 = r0 + 8 * LDS;
            ah[mf][0] = *reinterpret_cast<const uint32_t*>(&sQh[r0]);
            ah[mf][1] = *reinterpret_cast<const uint32_t*>(&sQh[r1]);
            ah[mf][2] = *reinterpret_cast<const uint32_t*>(&sQh[r0 + 8]);
            ah[mf][3] = *reinterpret_cast<const uint32_t*>(&sQh[r1 + 8]);
            al[mf][0] = *reinterpret_cast<const uint32_t*>(&sQl[r0]);
            al[mf][1] = *reinterpret_cast<const uint32_t*>(&sQl[r1]);
            al[mf][2] = *reinterpret_cast<const uint32_t*>(&sQl[r0 + 8]);
            al[mf][3] = *reinterpret_cast<const uint32_t*>(&sQl[r1 + 8]);
        }
#pragma unroll
        for (int nf = 0; nf < 4; ++nf) {
            const int r = (wn + nf * 8 + gi) * LDS + ks + tig * 2;
            b[nf][0] = *reinterpret_cast<const uint32_t*>(&sKh[r]);
            b[nf][1] = *reinterpret_cast<const uint32_t*>(&sKh[r + 8]);
        }
#pragma unroll
        for (int mf = 0; mf < 4; ++mf)
#pragma unroll
            for (int nf = 0; nf < 4; ++nf) {
                mma16816(acc[mf][nf], ah[mf], b[nf]);
                mma16816(acc[mf][nf], al[mf], b[nf]);
            }
#pragma unroll
        for (int nf = 0; nf < 4; ++nf) {
            const int r = (wn + nf * 8 + gi) * LDS + ks + tig * 2;
            b[nf][0] = *reinterpret_cast<const uint32_t*>(&sKl[r]);
            b[nf][1] = *reinterpret_cast<const uint32_t*>(&sKl[r + 8]);
        }
#pragma unroll
        for (int mf = 0; mf < 4; ++mf)
#pragma unroll
            for (int nf = 0; nf < 4; ++nf)
                mma16816(acc[mf][nf], ah[mf], b[nf]);
    }

    const float scale = 0.11785113019775793f;  // 1/sqrt(72)
    float* Sb = g_s + (size_t)bh * Nn * Nn;
#pragma unroll
    for (int mf = 0; mf < 4; ++mf)
#pragma unroll
        for (int nf = 0; nf < 4; ++nf) {
            const int row = m0 + wm + mf * 16 + gi;
            const int col = n0 + wn + nf * 8 + tig * 2;
            *reinterpret_cast<float2*>(&Sb[(size_t)row * Nn + col]) =
                make_float2(acc[mf][nf][0] * scale, acc[mf][nf][1] * scale);
            *reinterpret_cast<float2*>(&Sb[(size_t)(row + 8) * Nn + col]) =
                make_float2(acc[mf][nf][2] * scale, acc[mf][nf][3] * scale);
        }
}

// ---------------------------------------------------------------------------
// row softmax; reads fp32 S, writes P hi/lo bf16
// ---------------------------------------------------------------------------
__global__ __launch_bounds__(128) void k_softmax() {
    const size_t base = (size_t)blockIdx.x * Nn;
    const int tid = threadIdx.x;
    __shared__ float red[4];

    float v[8];
    float mx = -3.4e38f;
#pragma unroll
    for (int i = 0; i < 8; ++i) {
        v[i] = g_s[base + tid + i * 128];
        mx = fmaxf(mx, v[i]);
    }
#pragma unroll
    for (int o = 16; o > 0; o >>= 1) mx = fmaxf(mx, __shfl_xor_sync(0xffffffffu, mx, o));
    if ((tid & 31) == 0) red[tid >> 5] = mx;
    __syncthreads();
    mx = fmaxf(fmaxf(red[0], red[1]), fmaxf(red[2], red[3]));
    __syncthreads();

    float sum = 0.f;
#pragma unroll
    for (int i = 0; i < 8; ++i) {
        v[i] = __expf(v[i] - mx);
        sum += v[i];
    }
#pragma unroll
    for (int o = 16; o > 0; o >>= 1) sum += __shfl_xor_sync(0xffffffffu, sum, o);
    if ((tid & 31) == 0) red[tid >> 5] = sum;
    __syncthreads();
    const float inv = 1.0f / (red[0] + red[1] + red[2] + red[3]);

#pragma unroll
    for (int i = 0; i < 8; ++i) {
        const float p = v[i] * inv;
        const __nv_bfloat16 hi = __float2bfloat16(p);
        g_ph[base + tid + i * 128] = hi;
        g_pl[base + tid + i * 128] = __float2bfloat16(p - __bfloat162float(hi));
    }
}

// ---------------------------------------------------------------------------
// PV on HMMA: O[128 x 72] per (b,h,m-tile) = P[128,1024] @ V. B operand = V^T.
// 8 warps, each 16 rows x 72 cols (9 n-frags). BK=32. Writes g_oa hi/lo.
// ---------------------------------------------------------------------------
__global__ __launch_bounds__(256) void k_pv_tc() {
    constexpr int BK = 32, LDS = 40;
    __shared__ __align__(16) __nv_bfloat16 sPh[128 * LDS];
    __shared__ __align__(16) __nv_bfloat16 sPl[128 * LDS];
    __shared__ __align__(16) __nv_bfloat16 sVh[Dd * LDS];
    __shared__ __align__(16) __nv_bfloat16 sVl[Dd * LDS];

    const int tid  = threadIdx.x;
    const int warp = tid >> 5, lane = tid & 31;
    const int wm = warp * 16;
    const int gi  = lane >> 2;
    const int tig = lane & 3;
    const int bh = blockIdx.y;
    const int m0 = blockIdx.x * 128;

    const __nv_bfloat16* __restrict__ Ph = g_ph + (size_t)bh * Nn * Nn;
    const __nv_bfloat16* __restrict__ Pl = g_pl + (size_t)bh * Nn * Nn;
    const __nv_bfloat16* __restrict__ Vh = g_vth + (size_t)bh * Dd * Nn;
    const __nv_bfloat16* __restrict__ Vl = g_vtl + (size_t)bh * Dd * Nn;

    float acc[9][4] = {};

    for (int k0 = 0; k0 < Nn; k0 += BK) {
        if (k0) __syncthreads();
#pragma unroll
        for (int c = 0; c < 2; ++c) {
            const int chunk = tid + c * 256;
            const int row = chunk >> 2;
            const int kc  = chunk & 3;
            const int soff = row * LDS + kc * 8;
            const size_t gp = (size_t)(m0 + row) * Nn + k0 + kc * 8;
            *reinterpret_cast<uint4*>(&sPh[soff]) = *reinterpret_cast<const uint4*>(&Ph[gp]);
            *reinterpret_cast<uint4*>(&sPl[soff]) = *reinterpret_cast<const uint4*>(&Pl[gp]);
        }
        for (int idx = tid; idx < Dd * 4; idx += 256) {
            const int row = idx >> 2;
            const int kc  = idx & 3;
            const int soff = row * LDS + kc * 8;
            const size_t gv = (size_t)row * Nn + k0 + kc * 8;
            *reinterpret_cast<uint4*>(&sVh[soff]) = *reinterpret_cast<const uint4*>(&Vh[gv]);
            *reinterpret_cast<uint4*>(&sVl[soff]) = *reinterpret_cast<const uint4*>(&Vl[gv]);
        }
        __syncthreads();

#pragma unroll
        for (int ks = 0; ks < BK; ks += 16) {
            uint32_t ah[4], al[4], b[9][2];
            {
                const int r0 = (wm + gi) * LDS + ks + tig * 2;
                const int r1 = r0 + 8 * LDS;
                ah[0] = *reinterpret_cast<const uint32_t*>(&sPh[r0]);
                ah[1] = *reinterpret_cast<const uint32_t*>(&sPh[r1]);
                ah[2] = *reinterpret_cast<const uint32_t*>(&sPh[r0 + 8]);
                ah[3] = *reinterpret_cast<const uint32_t*>(&sPh[r1 + 8]);
                al[0] = *reinterpret_cast<const uint32_t*>(&sPl[r0]);
                al[1] = *reinterpret_cast<const uint32_t*>(&sPl[r1]);
                al[2] = *reinterpret_cast<const uint32_t*>(&sPl[r0 + 8]);
                al[3] = *reinterpret_cast<const uint32_t*>(&sPl[r1 + 8]);
            }
#pragma unroll
            for (int nf = 0; nf < 9; ++nf) {
                const int r = (nf * 8 + gi) * LDS + ks + tig * 2;
                b[nf][0] = *reinterpret_cast<const uint32_t*>(&sVh[r]);
                b[nf][1] = *reinterpret_cast<const uint32_t*>(&sVh[r + 8]);
            }
#pragma unroll
            for (int nf = 0; nf < 9; ++nf) {
                mma16816(acc[nf], ah, b[nf]);
                mma16816(acc[nf], al, b[nf]);
            }
#pragma unroll
            for (int nf = 0; nf < 9; ++nf) {
                const int r = (nf * 8 + gi) * LDS + ks + tig * 2;
                b[nf][0] = *reinterpret_cast<const uint32_t*>(&sVl[r]);
                b[nf][1] = *reinterpret_cast<const uint32_t*>(&sVl[r + 8]);
            }
#pragma unroll
            for (int nf = 0; nf < 9; ++nf)
                mma16816(acc[nf], ah, b[nf]);
        }
    }

    const int b = bh >> 4;
    const int h = bh & 15;
#pragma unroll
    for (int nf = 0; nf < 9; ++nf) {
        const int col = nf * 8 + tig * 2;
        const int tok0 = m0 + wm + gi;
        const size_t o0 = ((size_t)(b * Nn + tok0)) * HID + h * Dd + col;
        const size_t o1 = ((size_t)(b * Nn + tok0 + 8)) * HID + h * Dd + col;
        *reinterpret_cast<__nv_bfloat162*>(&g_oa_hi[o0]) = hilo2(acc[nf][0], acc[nf][1], false);
        *reinterpret_cast<__nv_bfloat162*>(&g_oa_lo[o0]) = hilo2(acc[nf][0], acc[nf][1], true);
        *reinterpret_cast<__nv_bfloat162*>(&g_oa_hi[o1]) = hilo2(acc[nf][2], acc[nf][3], false);
        *reinterpret_cast<__nv_bfloat162*>(&g_oa_lo[o1]) = hilo2(acc[nf][2], acc[nf][3], true);
    }
}

// ---------------------------------------------------------------------------
extern "C" void kernel_launch(void* const* d_in, const int* in_sizes, int n_in,
                              void* d_out, int out_size) {
    const float* x     = (const float*)d_in[0];
    const float* w_qkv = (const float*)d_in[1];
    const float* b_qkv = (const float*)d_in[2];
    const float* w_out = (const float*)d_in[3];
    const float* b_out = (const float*)d_in[4];
    float* out = (float*)d_out;

    constexpr int QKT_SMEM = 4 * 128 * 88 * 2;   // 90112
    static bool attr_done = false;
    if (!attr_done) {
        cudaFuncSetAttribute(k_qkt_tc, cudaFuncAttributeMaxDynamicSharedMemorySize, QKT_SMEM);
        attr_done = true;
    }

    const int n4 = MTOK * HID / 4;

    // prep
    k_zpad<<<(BHEAD * Nn + 255) / 256, 256>>>();
    k_split<<<(n4 + 255) / 256, 256>>>(x);
    k_tsplit<QKVN, 0><<<dim3(QKVN / 32, HID / 32), dim3(32, 8)>>>(w_qkv);
    k_tsplit<HID, 1><<<dim3(HID / 32, HID / 32), dim3(32, 8)>>>(w_out);

    // 1. QKV projection -> Q/K hi/lo (padded), V^T hi/lo
    k_gemm<0><<<dim3(QKVN / 128, MTOK / 128), 256>>>(b_qkv, nullptr);

    // 2. S = Q K^T * scale (HMMA)
    k_qkt_tc<<<dim3(Nn / 128, Nn / 128, BHEAD), 256, QKT_SMEM>>>();

    // 3. softmax -> P hi/lo
    k_softmax<<<BHEAD * Nn, 128>>>();

    // 4. O = P V (HMMA) -> g_oa hi/lo
    k_pv_tc<<<dim3(Nn / 128, BHEAD), 256>>>();

    // 5. output projection
    k_gemm<1><<<dim3(HID / 128, MTOK / 128), 256>>>(b_out, out);
}

// round 5
// speedup vs baseline: 3.1258x; 1.0496x over previous
#include <cuda_runtime.h>
#include <cuda_bf16.h>
#include <cstdint>

// ---------------------------------------------------------------------------
// Attention_21474836480706: B=4, N=1024, H=16, D=72, HID=1152 (fp32)
// R5: projections on HMMA hi/lo (unchanged); attention middle fused into a
// flash-attention kernel (online softmax, P in registers, no S/P scratch).
// ---------------------------------------------------------------------------

namespace {
constexpr int Bb    = 4;
constexpr int Nn    = 1024;
constexpr int Hh    = 16;
constexpr int Dd    = 72;
constexpr int DP    = 80;             // D padded to mult of 16
constexpr int HID   = 1152;
constexpr int ATT   = Hh * Dd;        // 1152
constexpr int MTOK  = Bb * Nn;        // 4096
constexpr int QKVN  = 3 * ATT;        // 3456
constexpr int BHEAD = Bb * Hh;        // 64
}

// ------------------------------ scratch ------------------------------------
__device__ __align__(16) __nv_bfloat16 g_qh[(size_t)BHEAD * Nn * DP];   // Q pre-scaled
__device__ __align__(16) __nv_bfloat16 g_ql[(size_t)BHEAD * Nn * DP];
__device__ __align__(16) __nv_bfloat16 g_kh[(size_t)BHEAD * Nn * DP];
__device__ __align__(16) __nv_bfloat16 g_kl[(size_t)BHEAD * Nn * DP];
__device__ __align__(16) __nv_bfloat16 g_vth[(size_t)BHEAD * Dd * Nn];  // V^T [bh][d][tok]
__device__ __align__(16) __nv_bfloat16 g_vtl[(size_t)BHEAD * Dd * Nn];

__device__ __align__(16) __nv_bfloat16 g_xa_hi[(size_t)MTOK * HID];
__device__ __align__(16) __nv_bfloat16 g_xa_lo[(size_t)MTOK * HID];
__device__ __align__(16) __nv_bfloat16 g_oa_hi[(size_t)MTOK * HID];
__device__ __align__(16) __nv_bfloat16 g_oa_lo[(size_t)MTOK * HID];
__device__ __align__(16) __nv_bfloat16 g_wqkvt_hi[(size_t)QKVN * HID];
__device__ __align__(16) __nv_bfloat16 g_wqkvt_lo[(size_t)QKVN * HID];
__device__ __align__(16) __nv_bfloat16 g_wot_hi[(size_t)HID * HID];
__device__ __align__(16) __nv_bfloat16 g_wot_lo[(size_t)HID * HID];

// --------------------------- helpers ---------------------------------------
__device__ __forceinline__ void mma16816(float* d, const uint32_t* a, const uint32_t* b) {
    asm volatile(
        "mma.sync.aligned.m16n8k16.row.col.f32.bf16.bf16.f32 "
        "{%0,%1,%2,%3}, {%4,%5,%6,%7}, {%8,%9}, {%0,%1,%2,%3};"
        : "+f"(d[0]), "+f"(d[1]), "+f"(d[2]), "+f"(d[3])
        : "r"(a[0]), "r"(a[1]), "r"(a[2]), "r"(a[3]), "r"(b[0]), "r"(b[1]));
}
__device__ __forceinline__ __nv_bfloat162 hilo2(float a, float b, bool lo) {
    __nv_bfloat16 ha = __float2bfloat16(a), hb = __float2bfloat16(b);
    if (!lo) return __halves2bfloat162(ha, hb);
    return __halves2bfloat162(__float2bfloat16(a - __bfloat162float(ha)),
                              __float2bfloat16(b - __bfloat162float(hb)));
}
__device__ __forceinline__ void pack_hilo(float a, float b, uint32_t& hi, uint32_t& lo) {
    __nv_bfloat16 ha = __float2bfloat16(a), hb = __float2bfloat16(b);
    __nv_bfloat162 h2 = __halves2bfloat162(ha, hb);
    __nv_bfloat162 l2 = __halves2bfloat162(__float2bfloat16(a - __bfloat162float(ha)),
                                           __float2bfloat16(b - __bfloat162float(hb)));
    hi = *reinterpret_cast<uint32_t*>(&h2);
    lo = *reinterpret_cast<uint32_t*>(&l2);
}

// ---------------------------------------------------------------------------
// zero D-padding columns (72..79) of Q/K hi/lo
// ---------------------------------------------------------------------------
__global__ __launch_bounds__(256) void k_zpad() {
    const int i = blockIdx.x * 256 + threadIdx.x;
    if (i >= BHEAD * Nn) return;
    const size_t o = (size_t)i * DP + Dd;
    const uint4 z = make_uint4(0, 0, 0, 0);
    *reinterpret_cast<uint4*>(&g_qh[o]) = z;
    *reinterpret_cast<uint4*>(&g_ql[o]) = z;
    *reinterpret_cast<uint4*>(&g_kh[o]) = z;
    *reinterpret_cast<uint4*>(&g_kl[o]) = z;
}

// ---------------------------------------------------------------------------
// split x fp32 -> bf16 hi+lo
// ---------------------------------------------------------------------------
__global__ __launch_bounds__(256) void k_split(const float* __restrict__ in) {
    const int n4 = MTOK * HID / 4;
    int i = blockIdx.x * 256 + threadIdx.x;
    if (i >= n4) return;
    float4 v = reinterpret_cast<const float4*>(in)[i];
    reinterpret_cast<__nv_bfloat162*>(g_xa_hi)[2 * i]     = hilo2(v.x, v.y, false);
    reinterpret_cast<__nv_bfloat162*>(g_xa_hi)[2 * i + 1] = hilo2(v.z, v.w, false);
    reinterpret_cast<__nv_bfloat162*>(g_xa_lo)[2 * i]     = hilo2(v.x, v.y, true);
    reinterpret_cast<__nv_bfloat162*>(g_xa_lo)[2 * i + 1] = hilo2(v.z, v.w, true);
}

// ---------------------------------------------------------------------------
// transpose + split: W[K][NCOLS] fp32 -> Wt hi/lo [NCOLS][K=1152] bf16
// ---------------------------------------------------------------------------
template <int NCOLS, int WHICH>
__global__ void k_tsplit(const float* __restrict__ W) {
    __shared__ float t[32][33];
    const int n0 = blockIdx.x * 32, k0 = blockIdx.y * 32;
    const int tx = threadIdx.x, ty = threadIdx.y;   // (32, 8)
#pragma unroll
    for (int i = 0; i < 4; ++i)
        t[ty * 4 + i][tx] = W[(size_t)(k0 + ty * 4 + i) * NCOLS + n0 + tx];
    __syncthreads();
    __nv_bfloat16* Hi = WHICH ? g_wot_hi : g_wqkvt_hi;
    __nv_bfloat16* Lo = WHICH ? g_wot_lo : g_wqkvt_lo;
#pragma unroll
    for (int i = 0; i < 4; ++i) {
        float v = t[tx][ty * 4 + i];
        __nv_bfloat16 h = __float2bfloat16(v);
        __nv_bfloat16 l = __float2bfloat16(v - __bfloat162float(h));
        size_t o = (size_t)(n0 + ty * 4 + i) * HID + k0 + tx;
        Hi[o] = h;
        Lo[o] = l;
    }
}

// ---------------------------------------------------------------------------
// HMMA GEMM (projections): C[128x128] = A[M,1152]*B^T, hi/lo 3-pass.
// MODE=0: scatter Q (pre-scaled by 1/sqrt(D)) / K hi/lo + V^T hi/lo, +b_qkv
// MODE=1: Cout = +b_out
// ---------------------------------------------------------------------------
template <int MODE>
__global__ __launch_bounds__(256) void k_gemm(const float* __restrict__ bias,
                                              float* __restrict__ Cout) {
    constexpr int BM = 128, BN = 128, BK = 32, LDS = 40;
    __shared__ __align__(16) __nv_bfloat16 sAh[BM * LDS];
    __shared__ __align__(16) __nv_bfloat16 sAl[BM * LDS];
    __shared__ __align__(16) __nv_bfloat16 sBh[BN * LDS];
    __shared__ __align__(16) __nv_bfloat16 sBl[BN * LDS];

    const int tid  = threadIdx.x;
    const int warp = tid >> 5, lane = tid & 31;
    const int wm = (warp >> 2) * 64;
    const int wn = (warp & 3) * 32;
    const int gi  = lane >> 2;
    const int tig = lane & 3;
    const int m0 = blockIdx.y * BM;
    const int n0 = blockIdx.x * BN;

    const __nv_bfloat16* __restrict__ Ah = MODE ? g_oa_hi : g_xa_hi;
    const __nv_bfloat16* __restrict__ Al = MODE ? g_oa_lo : g_xa_lo;
    const __nv_bfloat16* __restrict__ Bh = MODE ? g_wot_hi : g_wqkvt_hi;
    const __nv_bfloat16* __restrict__ Bl = MODE ? g_wot_lo : g_wqkvt_lo;

    float acc[4][4][4] = {};

    for (int k0 = 0; k0 < HID; k0 += BK) {
        if (k0) __syncthreads();
#pragma unroll
        for (int c = 0; c < 2; ++c) {
            const int chunk = tid + c * 256;
            const int row = chunk >> 2;
            const int kc  = chunk & 3;
            const int soff = row * LDS + kc * 8;
            const size_t ga = (size_t)(m0 + row) * HID + k0 + kc * 8;
            const size_t gb = (size_t)(n0 + row) * HID + k0 + kc * 8;
            *reinterpret_cast<uint4*>(&sAh[soff]) = *reinterpret_cast<const uint4*>(&Ah[ga]);
            *reinterpret_cast<uint4*>(&sAl[soff]) = *reinterpret_cast<const uint4*>(&Al[ga]);
            *reinterpret_cast<uint4*>(&sBh[soff]) = *reinterpret_cast<const uint4*>(&Bh[gb]);
            *reinterpret_cast<uint4*>(&sBl[soff]) = *reinterpret_cast<const uint4*>(&Bl[gb]);
        }
        __syncthreads();

#pragma unroll
        for (int ks = 0; ks < BK; ks += 16) {
            uint32_t ah[4][4], al[4][4], b[4][2];
#pragma unroll
            for (int mf = 0; mf < 4; ++mf) {
                const int r0 = (wm + mf * 16 + gi) * LDS + ks + tig * 2;
                const int r1 = r0 + 8 * LDS;
                ah[mf][0] = *reinterpret_cast<const uint32_t*>(&sAh[r0]);
                ah[mf][1] = *reinterpret_cast<const uint32_t*>(&sAh[r1]);
                ah[mf][2] = *reinterpret_cast<const uint32_t*>(&sAh[r0 + 8]);
                ah[mf][3] = *reinterpret_cast<const uint32_t*>(&sAh[r1 + 8]);
                al[mf][0] = *reinterpret_cast<const uint32_t*>(&sAl[r0]);
                al[mf][1] = *reinterpret_cast<const uint32_t*>(&sAl[r1]);
                al[mf][2] = *reinterpret_cast<const uint32_t*>(&sAl[r0 + 8]);
                al[mf][3] = *reinterpret_cast<const uint32_t*>(&sAl[r1 + 8]);
            }
#pragma unroll
            for (int nf = 0; nf < 4; ++nf) {
                const int r = (wn + nf * 8 + gi) * LDS + ks + tig * 2;
                b[nf][0] = *reinterpret_cast<const uint32_t*>(&sBh[r]);
                b[nf][1] = *reinterpret_cast<const uint32_t*>(&sBh[r + 8]);
            }
#pragma unroll
            for (int mf = 0; mf < 4; ++mf)
#pragma unroll
                for (int nf = 0; nf < 4; ++nf) {
                    mma16816(acc[mf][nf], ah[mf], b[nf]);
                    mma16816(acc[mf][nf], al[mf], b[nf]);
                }
#pragma unroll
            for (int nf = 0; nf < 4; ++nf) {
                const int r = (wn + nf * 8 + gi) * LDS + ks + tig * 2;
                b[nf][0] = *reinterpret_cast<const uint32_t*>(&sBl[r]);
                b[nf][1] = *reinterpret_cast<const uint32_t*>(&sBl[r + 8]);
            }
#pragma unroll
            for (int mf = 0; mf < 4; ++mf)
#pragma unroll
                for (int nf = 0; nf < 4; ++nf)
                    mma16816(acc[mf][nf], ah[mf], b[nf]);
        }
    }

    const float qscale = 0.11785113019775793f;  // 1/sqrt(72)
#pragma unroll
    for (int mf = 0; mf < 4; ++mf) {
#pragma unroll
        for (int nf = 0; nf < 4; ++nf) {
            const int row = m0 + wm + mf * 16 + gi;
            const int col = n0 + wn + nf * 8 + tig * 2;
            const float b0 = bias[col], b1 = bias[col + 1];
            float x0 = acc[mf][nf][0] + b0, y0 = acc[mf][nf][1] + b1;
            float x1 = acc[mf][nf][2] + b0, y1 = acc[mf][nf][3] + b1;
            if (MODE == 0) {
                const int which = n0 / ATT;
                const int rem = col - which * ATT;
                const int h = rem / Dd, d = rem - h * Dd;
                const int bb = row >> 10, tok = row & 1023;
                const int bh = bb * Hh + h;
                if (which < 2) {
                    if (which == 0) { x0 *= qscale; y0 *= qscale; x1 *= qscale; y1 *= qscale; }
                    __nv_bfloat16* Hi = which ? g_kh : g_qh;
                    __nv_bfloat16* Lo = which ? g_kl : g_ql;
                    const size_t o0 = ((size_t)bh * Nn + tok) * DP + d;
                    const size_t o1 = o0 + 8 * DP;
                    *reinterpret_cast<__nv_bfloat162*>(&Hi[o0]) = hilo2(x0, y0, false);
                    *reinterpret_cast<__nv_bfloat162*>(&Lo[o0]) = hilo2(x0, y0, true);
                    *reinterpret_cast<__nv_bfloat162*>(&Hi[o1]) = hilo2(x1, y1, false);
                    *reinterpret_cast<__nv_bfloat162*>(&Lo[o1]) = hilo2(x1, y1, true);
                } else {
                    const size_t b0o = ((size_t)bh * Dd + d) * Nn + tok;
                    const size_t b1o = b0o + Nn;
                    __nv_bfloat16 h0 = __float2bfloat16(x0);
                    __nv_bfloat16 h1 = __float2bfloat16(y0);
                    __nv_bfloat16 h2 = __float2bfloat16(x1);
                    __nv_bfloat16 h3 = __float2bfloat16(y1);
                    g_vth[b0o]     = h0;
                    g_vth[b1o]     = h1;
                    g_vth[b0o + 8] = h2;
                    g_vth[b1o + 8] = h3;
                    g_vtl[b0o]     = __float2bfloat16(x0 - __bfloat162float(h0));
                    g_vtl[b1o]     = __float2bfloat16(y0 - __bfloat162float(h1));
                    g_vtl[b0o + 8] = __float2bfloat16(x1 - __bfloat162float(h2));
                    g_vtl[b1o + 8] = __float2bfloat16(y1 - __bfloat162float(h3));
                }
            } else {
                *reinterpret_cast<float2*>(&Cout[(size_t)row * HID + col]) = make_float2(x0, y0);
                *reinterpret_cast<float2*>(&Cout[(size_t)(row + 8) * HID + col]) = make_float2(x1, y1);
            }
        }
    }
}

// ---------------------------------------------------------------------------
// Flash attention: per (bh, 128-query tile). 8 warps x 16 rows. Streams K/V
// in 128-token tiles; online softmax; P in registers (C-frag == A-frag).
// hi/lo 3-pass on both QK^T and PV. Output -> g_oa hi/lo [B,N,H*D].
// ---------------------------------------------------------------------------
namespace {
constexpr int LDSK = 88;                  // Q/K tile row stride (bf16)
constexpr int LDSV = 136;                 // V^T tile row stride (bf16)
constexpr int QELE = 128 * LDSK;          // 11264
constexpr int VELE = Dd * LDSV;           // 9792
constexpr int FLASH_SMEM = (4 * QELE + 2 * VELE) * 2;   // 129280 B
}

__global__ __launch_bounds__(256) void k_flash() {
    extern __shared__ __nv_bfloat16 sm[];
    __nv_bfloat16* sQh = sm;
    __nv_bfloat16* sQl = sm + QELE;
    __nv_bfloat16* sKh = sm + 2 * QELE;
    __nv_bfloat16* sKl = sm + 3 * QELE;
    __nv_bfloat16* sVh = sm + 4 * QELE;
    __nv_bfloat16* sVl = sm + 4 * QELE + VELE;

    const int tid  = threadIdx.x;
    const int warp = tid >> 5, lane = tid & 31;
    const int wm  = warp * 16;
    const int gi  = lane >> 2;
    const int tig = lane & 3;
    const int bh = blockIdx.y;
    const int m0 = blockIdx.x * 128;

    const __nv_bfloat16* __restrict__ Qh = g_qh + (size_t)bh * Nn * DP;
    const __nv_bfloat16* __restrict__ Ql = g_ql + (size_t)bh * Nn * DP;
    const __nv_bfloat16* __restrict__ Kh = g_kh + (size_t)bh * Nn * DP;
    const __nv_bfloat16* __restrict__ Kl = g_kl + (size_t)bh * Nn * DP;
    const __nv_bfloat16* __restrict__ Vh = g_vth + (size_t)bh * Dd * Nn;
    const __nv_bfloat16* __restrict__ Vl = g_vtl + (size_t)bh * Dd * Nn;

    // load Q tile (hi/lo), 10 uint4 per row
#pragma unroll
    for (int c = 0; c < 5; ++c) {
        const int chunk = tid + c * 256;      // 0..1279
        const int row = chunk / 10;
        const int kc  = chunk - row * 10;
        const int soff = row * LDSK + kc * 8;
        const size_t gq = (size_t)(m0 + row) * DP + kc * 8;
        *reinterpret_cast<uint4*>(&sQh[soff]) = *reinterpret_cast<const uint4*>(&Qh[gq]);
        *reinterpret_cast<uint4*>(&sQl[soff]) = *reinterpret_cast<const uint4*>(&Ql[gq]);
    }

    float m_run0 = -3.4e38f, m_run1 = -3.4e38f;
    float l_run0 = 0.f, l_run1 = 0.f;
    float o[9][4] = {};

    for (int kt = 0; kt < Nn / 128; ++kt) {
        const int n0 = kt * 128;
        // load K tile (hi/lo)
#pragma unroll
        for (int c = 0; c < 5; ++c) {
            const int chunk = tid + c * 256;
            const int row = chunk / 10;
            const int kc  = chunk - row * 10;
            const int soff = row * LDSK + kc * 8;
            const size_t gk = (size_t)(n0 + row) * DP + kc * 8;
            *reinterpret_cast<uint4*>(&sKh[soff]) = *reinterpret_cast<const uint4*>(&Kh[gk]);
            *reinterpret_cast<uint4*>(&sKl[soff]) = *reinterpret_cast<const uint4*>(&Kl[gk]);
        }
        __syncthreads();   // K (and on kt==0, Q) ready; prev iter's K reads done

        // S = Q K^T (scaled Q), 3-pass. s[nf]: rows (wm+gi, +8), cols nf*8+tig*2
        float s[16][4];
#pragma unroll
        for (int nf = 0; nf < 16; ++nf)
            s[nf][0] = s[nf][1] = s[nf][2] = s[nf][3] = 0.f;
#pragma unroll
        for (int ks = 0; ks < DP; ks += 16) {
            uint32_t aH[4], aL[4];
            const int r0 = (wm + gi) * LDSK + ks + tig * 2;
            const int r1 = r0 + 8 * LDSK;
            aH[0] = *reinterpret_cast<const uint32_t*>(&sQh[r0]);
            aH[1] = *reinterpret_cast<const uint32_t*>(&sQh[r1]);
            aH[2] = *reinterpret_cast<const uint32_t*>(&sQh[r0 + 8]);
            aH[3] = *reinterpret_cast<const uint32_t*>(&sQh[r1 + 8]);
            aL[0] = *reinterpret_cast<const uint32_t*>(&sQl[r0]);
            aL[1] = *reinterpret_cast<const uint32_t*>(&sQl[r1]);
            aL[2] = *reinterpret_cast<const uint32_t*>(&sQl[r0 + 8]);
            aL[3] = *reinterpret_cast<const uint32_t*>(&sQl[r1 + 8]);
#pragma unroll
            for (int nf = 0; nf < 16; ++nf) {
                const int r = (nf * 8 + gi) * LDSK + ks + tig * 2;
                uint32_t b[2];
                b[0] = *reinterpret_cast<const uint32_t*>(&sKh[r]);
                b[1] = *reinterpret_cast<const uint32_t*>(&sKh[r + 8]);
                mma16816(s[nf], aH, b);
                mma16816(s[nf], aL, b);
            }
#pragma unroll
            for (int nf = 0; nf < 16; ++nf) {
                const int r = (nf * 8 + gi) * LDSK + ks + tig * 2;
                uint32_t b[2];
                b[0] = *reinterpret_cast<const uint32_t*>(&sKl[r]);
                b[1] = *reinterpret_cast<const uint32_t*>(&sKl[r + 8]);
                mma16816(s[nf], aH, b);
            }
        }

        // online softmax (rows owned within warp; reduce over tig = lane bits 0..1)
        float mt0 = -3.4e38f, mt1 = -3.4e38f;
#pragma unroll
        for (int nf = 0; nf < 16; ++nf) {
            mt0 = fmaxf(mt0, fmaxf(s[nf][0], s[nf][1]));
            mt1 = fmaxf(mt1, fmaxf(s[nf][2], s[nf][3]));
        }
        mt0 = fmaxf(mt0, __shfl_xor_sync(0xffffffffu, mt0, 1));
        mt0 = fmaxf(mt0, __shfl_xor_sync(0xffffffffu, mt0, 2));
        mt1 = fmaxf(mt1, __shfl_xor_sync(0xffffffffu, mt1, 1));
        mt1 = fmaxf(mt1, __shfl_xor_sync(0xffffffffu, mt1, 2));
        const float mn0 = fmaxf(m_run0, mt0);
        const float mn1 = fmaxf(m_run1, mt1);
        const float sc0 = __expf(m_run0 - mn0);
        const float sc1 = __expf(m_run1 - mn1);

        uint32_t pH[8][4], pL[8][4];
        float ps0 = 0.f, ps1 = 0.f;
#pragma unroll
        for (int kc = 0; kc < 8; ++kc) {
            const int nf0 = 2 * kc, nf1 = 2 * kc + 1;
            const float p00 = __expf(s[nf0][0] - mn0), p01 = __expf(s[nf0][1] - mn0);
            const float p02 = __expf(s[nf0][2] - mn1), p03 = __expf(s[nf0][3] - mn1);
            const float p10 = __expf(s[nf1][0] - mn0), p11 = __expf(s[nf1][1] - mn0);
            const float p12 = __expf(s[nf1][2] - mn1), p13 = __expf(s[nf1][3] - mn1);
            ps0 += p00 + p01 + p10 + p11;
            ps1 += p02 + p03 + p12 + p13;
            pack_hilo(p00, p01, pH[kc][0], pL[kc][0]);
            pack_hilo(p02, p03, pH[kc][1], pL[kc][1]);
            pack_hilo(p10, p11, pH[kc][2], pL[kc][2]);
            pack_hilo(p12, p13, pH[kc][3], pL[kc][3]);
        }
        ps0 += __shfl_xor_sync(0xffffffffu, ps0, 1);
        ps0 += __shfl_xor_sync(0xffffffffu, ps0, 2);
        ps1 += __shfl_xor_sync(0xffffffffu, ps1, 1);
        ps1 += __shfl_xor_sync(0xffffffffu, ps1, 2);
        l_run0 = l_run0 * sc0 + ps0;
        l_run1 = l_run1 * sc1 + ps1;
        m_run0 = mn0;
        m_run1 = mn1;
#pragma unroll
        for (int nf = 0; nf < 9; ++nf) {
            o[nf][0] *= sc0; o[nf][1] *= sc0;
            o[nf][2] *= sc1; o[nf][3] *= sc1;
        }

        // load V^T tile (hi/lo): rows d 0..71, 16 uint4 each
        for (int idx = tid; idx < Dd * 16; idx += 256) {
            const int row = idx >> 4;
            const int kc  = idx & 15;
            const int soff = row * LDSV + kc * 8;
            const size_t gv = (size_t)row * Nn + n0 + kc * 8;
            *reinterpret_cast<uint4*>(&sVh[soff]) = *reinterpret_cast<const uint4*>(&Vh[gv]);
            *reinterpret_cast<uint4*>(&sVl[soff]) = *reinterpret_cast<const uint4*>(&Vl[gv]);
        }
        __syncthreads();   // V ready; also: all warps past S-MMA (sK safe to refill)

        // O += P V, 3-pass
#pragma unroll
        for (int kc = 0; kc < 8; ++kc) {
#pragma unroll
            for (int nf = 0; nf < 9; ++nf) {
                const int r = (nf * 8 + gi) * LDSV + kc * 16 + tig * 2;
                uint32_t b[2];
                b[0] = *reinterpret_cast<const uint32_t*>(&sVh[r]);
                b[1] = *reinterpret_cast<const uint32_t*>(&sVh[r + 8]);
                mma16816(o[nf], pH[kc], b);
                mma16816(o[nf], pL[kc], b);
                b[0] = *reinterpret_cast<const uint32_t*>(&sVl[r]);
                b[1] = *reinterpret_cast<const uint32_t*>(&sVl[r + 8]);
                mma16816(o[nf], pH[kc], b);
            }
        }
    }

    // epilogue: O /= l; write bf16 hi/lo to [B,N,H*D]
    const float inv0 = 1.0f / l_run0;
    const float inv1 = 1.0f / l_run1;
    const int b = bh >> 4;
    const int h = bh & 15;
    const int tok0 = m0 + wm + gi;
#pragma unroll
    for (int nf = 0; nf < 9; ++nf) {
        const int col = nf * 8 + tig * 2;
        const size_t o0 = ((size_t)(b * Nn + tok0)) * HID + h * Dd + col;
        const size_t o1 = ((size_t)(b * Nn + tok0 + 8)) * HID + h * Dd + col;
        const float x0 = o[nf][0] * inv0, y0 = o[nf][1] * inv0;
        const float x1 = o[nf][2] * inv1, y1 = o[nf][3] * inv1;
        *reinterpret_cast<__nv_bfloat162*>(&g_oa_hi[o0]) = hilo2(x0, y0, false);
        *reinterpret_cast<__nv_bfloat162*>(&g_oa_lo[o0]) = hilo2(x0, y0, true);
        *reinterpret_cast<__nv_bfloat162*>(&g_oa_hi[o1]) = hilo2(x1, y1, false);
        *reinterpret_cast<__nv_bfloat162*>(&g_oa_lo[o1]) = hilo2(x1, y1, true);
    }
}

// ---------------------------------------------------------------------------
extern "C" void kernel_launch(void* const* d_in, const int* in_sizes, int n_in,
                              void* d_out, int out_size) {
    const float* x     = (const float*)d_in[0];
    const float* w_qkv = (const float*)d_in[1];
    const float* b_qkv = (const float*)d_in[2];
    const float* w_out = (const float*)d_in[3];
    const float* b_out = (const float*)d_in[4];
    float* out = (float*)d_out;

    cudaFuncSetAttribute(k_flash, cudaFuncAttributeMaxDynamicSharedMemorySize, FLASH_SMEM);

    const int n4 = MTOK * HID / 4;

    // prep
    k_zpad<<<(BHEAD * Nn + 255) / 256, 256>>>();
    k_split<<<(n4 + 255) / 256, 256>>>(x);
    k_tsplit<QKVN, 0><<<dim3(QKVN / 32, HID / 32), dim3(32, 8)>>>(w_qkv);
    k_tsplit<HID, 1><<<dim3(HID / 32, HID / 32), dim3(32, 8)>>>(w_out);

    // 1. QKV projection -> Q(scaled)/K hi/lo (padded), V^T hi/lo
    k_gemm<0><<<dim3(QKVN / 128, MTOK / 128), 256>>>(b_qkv, nullptr);

    // 2. fused flash attention -> g_oa hi/lo
    k_flash<<<dim3(Nn / 128, BHEAD), 256, FLASH_SMEM>>>();

    // 3. output projection
    k_gemm<1><<<dim3(HID / 128, MTOK / 128), 256>>>(b_out, out);
}

// round 6
// speedup vs baseline: 3.7627x; 1.2038x over previous
#include <cuda_runtime.h>
#include <cuda_bf16.h>
#include <cstdint>

// ---------------------------------------------------------------------------
// Attention_21474836480706: B=4, N=1024, H=16, D=72, HID=1152 (fp32)
// R6: cp.async pipelining — k_gemm double-buffered (2-stage), flash K/V loads
// overlapped with MMA. Math identical to R5 (hi/lo bf16 3-pass everywhere).
// ---------------------------------------------------------------------------

namespace {
constexpr int Bb    = 4;
constexpr int Nn    = 1024;
constexpr int Hh    = 16;
constexpr int Dd    = 72;
constexpr int DP    = 80;
constexpr int HID   = 1152;
constexpr int ATT   = Hh * Dd;        // 1152
constexpr int MTOK  = Bb * Nn;        // 4096
constexpr int QKVN  = 3 * ATT;        // 3456
constexpr int BHEAD = Bb * Hh;        // 64
}

// ------------------------------ scratch ------------------------------------
__device__ __align__(16) __nv_bfloat16 g_qh[(size_t)BHEAD * Nn * DP];   // Q pre-scaled
__device__ __align__(16) __nv_bfloat16 g_ql[(size_t)BHEAD * Nn * DP];
__device__ __align__(16) __nv_bfloat16 g_kh[(size_t)BHEAD * Nn * DP];
__device__ __align__(16) __nv_bfloat16 g_kl[(size_t)BHEAD * Nn * DP];
__device__ __align__(16) __nv_bfloat16 g_vth[(size_t)BHEAD * Dd * Nn];  // V^T [bh][d][tok]
__device__ __align__(16) __nv_bfloat16 g_vtl[(size_t)BHEAD * Dd * Nn];

__device__ __align__(16) __nv_bfloat16 g_xa_hi[(size_t)MTOK * HID];
__device__ __align__(16) __nv_bfloat16 g_xa_lo[(size_t)MTOK * HID];
__device__ __align__(16) __nv_bfloat16 g_oa_hi[(size_t)MTOK * HID];
__device__ __align__(16) __nv_bfloat16 g_oa_lo[(size_t)MTOK * HID];
__device__ __align__(16) __nv_bfloat16 g_wqkvt_hi[(size_t)QKVN * HID];
__device__ __align__(16) __nv_bfloat16 g_wqkvt_lo[(size_t)QKVN * HID];
__device__ __align__(16) __nv_bfloat16 g_wot_hi[(size_t)HID * HID];
__device__ __align__(16) __nv_bfloat16 g_wot_lo[(size_t)HID * HID];

// --------------------------- helpers ---------------------------------------
__device__ __forceinline__ uint32_t smem_u32(const void* p) {
    uint32_t a;
    asm("{ .reg .u64 t; cvta.to.shared.u64 t, %1; cvt.u32.u64 %0, t; }" : "=r"(a) : "l"(p));
    return a;
}
__device__ __forceinline__ void cp16(uint32_t s, const void* g) {
    asm volatile("cp.async.cg.shared.global [%0], [%1], 16;" :: "r"(s), "l"(g));
}
#define CP_COMMIT() asm volatile("cp.async.commit_group;" ::: "memory")
#define CP_WAIT(n)  asm volatile("cp.async.wait_group %0;" :: "n"(n) : "memory")

__device__ __forceinline__ void mma16816(float* d, const uint32_t* a, const uint32_t* b) {
    asm volatile(
        "mma.sync.aligned.m16n8k16.row.col.f32.bf16.bf16.f32 "
        "{%0,%1,%2,%3}, {%4,%5,%6,%7}, {%8,%9}, {%0,%1,%2,%3};"
        : "+f"(d[0]), "+f"(d[1]), "+f"(d[2]), "+f"(d[3])
        : "r"(a[0]), "r"(a[1]), "r"(a[2]), "r"(a[3]), "r"(b[0]), "r"(b[1]));
}
__device__ __forceinline__ __nv_bfloat162 hilo2(float a, float b, bool lo) {
    __nv_bfloat16 ha = __float2bfloat16(a), hb = __float2bfloat16(b);
    if (!lo) return __halves2bfloat162(ha, hb);
    return __halves2bfloat162(__float2bfloat16(a - __bfloat162float(ha)),
                              __float2bfloat16(b - __bfloat162float(hb)));
}
__device__ __forceinline__ void pack_hilo(float a, float b, uint32_t& hi, uint32_t& lo) {
    __nv_bfloat16 ha = __float2bfloat16(a), hb = __float2bfloat16(b);
    __nv_bfloat162 h2 = __halves2bfloat162(ha, hb);
    __nv_bfloat162 l2 = __halves2bfloat162(__float2bfloat16(a - __bfloat162float(ha)),
                                           __float2bfloat16(b - __bfloat162float(hb)));
    hi = *reinterpret_cast<uint32_t*>(&h2);
    lo = *reinterpret_cast<uint32_t*>(&l2);
}

// ---------------------------------------------------------------------------
__global__ __launch_bounds__(256) void k_zpad() {
    const int i = blockIdx.x * 256 + threadIdx.x;
    if (i >= BHEAD * Nn) return;
    const size_t o = (size_t)i * DP + Dd;
    const uint4 z = make_uint4(0, 0, 0, 0);
    *reinterpret_cast<uint4*>(&g_qh[o]) = z;
    *reinterpret_cast<uint4*>(&g_ql[o]) = z;
    *reinterpret_cast<uint4*>(&g_kh[o]) = z;
    *reinterpret_cast<uint4*>(&g_kl[o]) = z;
}

__global__ __launch_bounds__(256) void k_split(const float* __restrict__ in) {
    const int n4 = MTOK * HID / 4;
    int i = blockIdx.x * 256 + threadIdx.x;
    if (i >= n4) return;
    float4 v = reinterpret_cast<const float4*>(in)[i];
    reinterpret_cast<__nv_bfloat162*>(g_xa_hi)[2 * i]     = hilo2(v.x, v.y, false);
    reinterpret_cast<__nv_bfloat162*>(g_xa_hi)[2 * i + 1] = hilo2(v.z, v.w, false);
    reinterpret_cast<__nv_bfloat162*>(g_xa_lo)[2 * i]     = hilo2(v.x, v.y, true);
    reinterpret_cast<__nv_bfloat162*>(g_xa_lo)[2 * i + 1] = hilo2(v.z, v.w, true);
}

template <int NCOLS, int WHICH>
__global__ void k_tsplit(const float* __restrict__ W) {
    __shared__ float t[32][33];
    const int n0 = blockIdx.x * 32, k0 = blockIdx.y * 32;
    const int tx = threadIdx.x, ty = threadIdx.y;   // (32, 8)
#pragma unroll
    for (int i = 0; i < 4; ++i)
        t[ty * 4 + i][tx] = W[(size_t)(k0 + ty * 4 + i) * NCOLS + n0 + tx];
    __syncthreads();
    __nv_bfloat16* Hi = WHICH ? g_wot_hi : g_wqkvt_hi;
    __nv_bfloat16* Lo = WHICH ? g_wot_lo : g_wqkvt_lo;
#pragma unroll
    for (int i = 0; i < 4; ++i) {
        float v = t[tx][ty * 4 + i];
        __nv_bfloat16 h = __float2bfloat16(v);
        __nv_bfloat16 l = __float2bfloat16(v - __bfloat162float(h));
        size_t o = (size_t)(n0 + ty * 4 + i) * HID + k0 + tx;
        Hi[o] = h;
        Lo[o] = l;
    }
}

// ---------------------------------------------------------------------------
// HMMA GEMM (projections), 2-stage cp.async double buffer.
// ---------------------------------------------------------------------------
namespace {
constexpr int GBM = 128, GBK = 32, GLDS = 40;
constexpr int GTILE = GBM * GLDS;                 // elems per operand tile
constexpr int GSTAGE = 4 * GTILE;                 // Ah,Al,Bh,Bl
constexpr int GEMM_SMEM = 2 * GSTAGE * 2;         // bytes = 81920
}

template <int MODE>
__global__ __launch_bounds__(256) void k_gemm(const float* __restrict__ bias,
                                              float* __restrict__ Cout) {
    extern __shared__ __nv_bfloat16 gsm[];

    const int tid  = threadIdx.x;
    const int warp = tid >> 5, lane = tid & 31;
    const int wm = (warp >> 2) * 64;
    const int wn = (warp & 3) * 32;
    const int gi  = lane >> 2;
    const int tig = lane & 3;
    const int m0 = blockIdx.y * GBM;
    const int n0 = blockIdx.x * GBM;

    const __nv_bfloat16* __restrict__ Ah = MODE ? g_oa_hi : g_xa_hi;
    const __nv_bfloat16* __restrict__ Al = MODE ? g_oa_lo : g_xa_lo;
    const __nv_bfloat16* __restrict__ Bh = MODE ? g_wot_hi : g_wqkvt_hi;
    const __nv_bfloat16* __restrict__ Bl = MODE ? g_wot_lo : g_wqkvt_lo;

    // this thread's two load slots (row, k-chunk)
    const int r0c = tid >> 2, k0c = (tid & 3);            // chunk set 0
    const int r1c = (tid + 256) >> 2, k1c = (tid & 3);    // chunk set 1

    auto issue_tile = [&](int kt, int stage) {
        __nv_bfloat16* base = gsm + stage * GSTAGE;
        const int kk = kt * GBK;
#pragma unroll
        for (int c = 0; c < 2; ++c) {
            const int row = c ? r1c : r0c;
            const int kc  = c ? k1c : k0c;
            const uint32_t soff = smem_u32(base + row * GLDS + kc * 8);
            const size_t ga = (size_t)(m0 + row) * HID + kk + kc * 8;
            const size_t gb = (size_t)(n0 + row) * HID + kk + kc * 8;
            cp16(soff,                      Ah + ga);
            cp16(soff + GTILE * 2,          Al + ga);
            cp16(soff + 2 * GTILE * 2,      Bh + gb);
            cp16(soff + 3 * GTILE * 2,      Bl + gb);
        }
        CP_COMMIT();
    };

    float acc[4][4][4] = {};
    constexpr int NT = HID / GBK;   // 36

    issue_tile(0, 0);

    for (int t = 0; t < NT; ++t) {
        if (t + 1 < NT) {
            issue_tile(t + 1, (t + 1) & 1);
            CP_WAIT(1);
        } else {
            CP_WAIT(0);
        }
        __syncthreads();

        const __nv_bfloat16* sAh = gsm + (t & 1) * GSTAGE;
        const __nv_bfloat16* sAl = sAh + GTILE;
        const __nv_bfloat16* sBh = sAh + 2 * GTILE;
        const __nv_bfloat16* sBl = sAh + 3 * GTILE;

#pragma unroll
        for (int ks = 0; ks < GBK; ks += 16) {
            uint32_t ah[4][4], al[4][4], b[4][2];
#pragma unroll
            for (int mf = 0; mf < 4; ++mf) {
                const int q0 = (wm + mf * 16 + gi) * GLDS + ks + tig * 2;
                const int q1 = q0 + 8 * GLDS;
                ah[mf][0] = *reinterpret_cast<const uint32_t*>(&sAh[q0]);
                ah[mf][1] = *reinterpret_cast<const uint32_t*>(&sAh[q1]);
                ah[mf][2] = *reinterpret_cast<const uint32_t*>(&sAh[q0 + 8]);
                ah[mf][3] = *reinterpret_cast<const uint32_t*>(&sAh[q1 + 8]);
                al[mf][0] = *reinterpret_cast<const uint32_t*>(&sAl[q0]);
                al[mf][1] = *reinterpret_cast<const uint32_t*>(&sAl[q1]);
                al[mf][2] = *reinterpret_cast<const uint32_t*>(&sAl[q0 + 8]);
                al[mf][3] = *reinterpret_cast<const uint32_t*>(&sAl[q1 + 8]);
            }
#pragma unroll
            for (int nf = 0; nf < 4; ++nf) {
                const int r = (wn + nf * 8 + gi) * GLDS + ks + tig * 2;
                b[nf][0] = *reinterpret_cast<const uint32_t*>(&sBh[r]);
                b[nf][1] = *reinterpret_cast<const uint32_t*>(&sBh[r + 8]);
            }
#pragma unroll
            for (int mf = 0; mf < 4; ++mf)
#pragma unroll
                for (int nf = 0; nf < 4; ++nf) {
                    mma16816(acc[mf][nf], ah[mf], b[nf]);
                    mma16816(acc[mf][nf], al[mf], b[nf]);
                }
#pragma unroll
            for (int nf = 0; nf < 4; ++nf) {
                const int r = (wn + nf * 8 + gi) * GLDS + ks + tig * 2;
                b[nf][0] = *reinterpret_cast<const uint32_t*>(&sBl[r]);
                b[nf][1] = *reinterpret_cast<const uint32_t*>(&sBl[r + 8]);
            }
#pragma unroll
            for (int mf = 0; mf < 4; ++mf)
#pragma unroll
                for (int nf = 0; nf < 4; ++nf)
                    mma16816(acc[mf][nf], ah[mf], b[nf]);
        }
        __syncthreads();
    }

    const float qscale = 0.11785113019775793f;  // 1/sqrt(72)
#pragma unroll
    for (int mf = 0; mf < 4; ++mf) {
#pragma unroll
        for (int nf = 0; nf < 4; ++nf) {
            const int row = m0 + wm + mf * 16 + gi;
            const int col = n0 + wn + nf * 8 + tig * 2;
            const float b0 = bias[col], b1 = bias[col + 1];
            float x0 = acc[mf][nf][0] + b0, y0 = acc[mf][nf][1] + b1;
            float x1 = acc[mf][nf][2] + b0, y1 = acc[mf][nf][3] + b1;
            if (MODE == 0) {
                const int which = n0 / ATT;
                const int rem = col - which * ATT;
                const int h = rem / Dd, d = rem - h * Dd;
                const int bb = row >> 10, tok = row & 1023;
                const int bh = bb * Hh + h;
                if (which < 2) {
                    if (which == 0) { x0 *= qscale; y0 *= qscale; x1 *= qscale; y1 *= qscale; }
                    __nv_bfloat16* Hi = which ? g_kh : g_qh;
                    __nv_bfloat16* Lo = which ? g_kl : g_ql;
                    const size_t o0 = ((size_t)bh * Nn + tok) * DP + d;
                    const size_t o1 = o0 + 8 * DP;
                    *reinterpret_cast<__nv_bfloat162*>(&Hi[o0]) = hilo2(x0, y0, false);
                    *reinterpret_cast<__nv_bfloat162*>(&Lo[o0]) = hilo2(x0, y0, true);
                    *reinterpret_cast<__nv_bfloat162*>(&Hi[o1]) = hilo2(x1, y1, false);
                    *reinterpret_cast<__nv_bfloat162*>(&Lo[o1]) = hilo2(x1, y1, true);
                } else {
                    const size_t b0o = ((size_t)bh * Dd + d) * Nn + tok;
                    const size_t b1o = b0o + Nn;
                    __nv_bfloat16 h0 = __float2bfloat16(x0);
                    __nv_bfloat16 h1 = __float2bfloat16(y0);
                    __nv_bfloat16 h2 = __float2bfloat16(x1);
                    __nv_bfloat16 h3 = __float2bfloat16(y1);
                    g_vth[b0o]     = h0;
                    g_vth[b1o]     = h1;
                    g_vth[b0o + 8] = h2;
                    g_vth[b1o + 8] = h3;
                    g_vtl[b0o]     = __float2bfloat16(x0 - __bfloat162float(h0));
                    g_vtl[b1o]     = __float2bfloat16(y0 - __bfloat162float(h1));
                    g_vtl[b0o + 8] = __float2bfloat16(x1 - __bfloat162float(h2));
                    g_vtl[b1o + 8] = __float2bfloat16(y1 - __bfloat162float(h3));
                }
            } else {
                *reinterpret_cast<float2*>(&Cout[(size_t)row * HID + col]) = make_float2(x0, y0);
                *reinterpret_cast<float2*>(&Cout[(size_t)(row + 8) * HID + col]) = make_float2(x1, y1);
            }
        }
    }
}

// ---------------------------------------------------------------------------
// Flash attention with cp.async pipelining:
//   V(kt) streams during S-MMA+softmax; K(kt+1) streams during PV-MMA.
// ---------------------------------------------------------------------------
namespace {
constexpr int LDSK = 88;
constexpr int LDSV = 136;
constexpr int QELE = 128 * LDSK;          // 11264
constexpr int VELE = Dd * LDSV;           // 9792
constexpr int FLASH_SMEM = (4 * QELE + 2 * VELE) * 2;   // 129280 B
}

__global__ __launch_bounds__(256) void k_flash() {
    extern __shared__ __nv_bfloat16 sm[];
    __nv_bfloat16* sQh = sm;
    __nv_bfloat16* sQl = sm + QELE;
    __nv_bfloat16* sKh = sm + 2 * QELE;
    __nv_bfloat16* sKl = sm + 3 * QELE;
    __nv_bfloat16* sVh = sm + 4 * QELE;
    __nv_bfloat16* sVl = sm + 4 * QELE + VELE;

    const int tid  = threadIdx.x;
    const int warp = tid >> 5, lane = tid & 31;
    const int wm  = warp * 16;
    const int gi  = lane >> 2;
    const int tig = lane & 3;
    const int bh = blockIdx.y;
    const int m0 = blockIdx.x * 128;

    const __nv_bfloat16* __restrict__ Qh = g_qh + (size_t)bh * Nn * DP;
    const __nv_bfloat16* __restrict__ Ql = g_ql + (size_t)bh * Nn * DP;
    const __nv_bfloat16* __restrict__ Kh = g_kh + (size_t)bh * Nn * DP;
    const __nv_bfloat16* __restrict__ Kl = g_kl + (size_t)bh * Nn * DP;
    const __nv_bfloat16* __restrict__ Vh = g_vth + (size_t)bh * Dd * Nn;
    const __nv_bfloat16* __restrict__ Vl = g_vtl + (size_t)bh * Dd * Nn;

    auto issueK = [&](int kt) {
        const int nn = kt * 128;
#pragma unroll
        for (int c = 0; c < 5; ++c) {
            const int chunk = tid + c * 256;
            const int row = chunk / 10;
            const int kc  = chunk - row * 10;
            const uint32_t soff = smem_u32(sKh + row * LDSK + kc * 8);
            const size_t gk = (size_t)(nn + row) * DP + kc * 8;
            cp16(soff, Kh + gk);
            cp16(soff + 2 * QELE, Kl + gk);   // sKl = sKh + QELE elems = +2*QELE bytes? no:
        }
        CP_COMMIT();
    };
    // NOTE: sKl is QELE elems after sKh -> byte offset QELE*2. Fix inside issueK:
    // (implemented below correctly; lambda above replaced)

    auto issueK2 = [&](int kt) {
        const int nn = kt * 128;
#pragma unroll
        for (int c = 0; c < 5; ++c) {
            const int chunk = tid + c * 256;
            const int row = chunk / 10;
            const int kc  = chunk - row * 10;
            const size_t gk = (size_t)(nn + row) * DP + kc * 8;
            cp16(smem_u32(sKh + row * LDSK + kc * 8), Kh + gk);
            cp16(smem_u32(sKl + row * LDSK + kc * 8), Kl + gk);
        }
        CP_COMMIT();
    };

    auto issueV = [&](int kt) {
        const int nn = kt * 128;
        for (int idx = tid; idx < Dd * 16; idx += 256) {
            const int row = idx >> 4;
            const int kc  = idx & 15;
            const size_t gv = (size_t)row * Nn + nn + kc * 8;
            cp16(smem_u32(sVh + row * LDSV + kc * 8), Vh + gv);
            cp16(smem_u32(sVl + row * LDSV + kc * 8), Vl + gv);
        }
        CP_COMMIT();
    };
    (void)issueK;

    // load Q tile (direct) + prefetch K0
    issueK2(0);
#pragma unroll
    for (int c = 0; c < 5; ++c) {
        const int chunk = tid + c * 256;
        const int row = chunk / 10;
        const int kc  = chunk - row * 10;
        const int soff = row * LDSK + kc * 8;
        const size_t gq = (size_t)(m0 + row) * DP + kc * 8;
        *reinterpret_cast<uint4*>(&sQh[soff]) = *reinterpret_cast<const uint4*>(&Qh[gq]);
        *reinterpret_cast<uint4*>(&sQl[soff]) = *reinterpret_cast<const uint4*>(&Ql[gq]);
    }

    float m_run0 = -3.4e38f, m_run1 = -3.4e38f;
    float l_run0 = 0.f, l_run1 = 0.f;
    float o[9][4] = {};

    for (int kt = 0; kt < Nn / 128; ++kt) {
        CP_WAIT(0);        // K(kt) arrived (V/K groups from prev iter drained earlier)
        __syncthreads();   // K visible to all; V buffer free (prev PV done by all)

        issueV(kt);        // V streams during S-MMA + softmax

        // S = Q K^T, 3-pass
        float s[16][4];
#pragma unroll
        for (int nf = 0; nf < 16; ++nf)
            s[nf][0] = s[nf][1] = s[nf][2] = s[nf][3] = 0.f;
#pragma unroll
        for (int ks = 0; ks < DP; ks += 16) {
            uint32_t aH[4], aL[4];
            const int q0 = (wm + gi) * LDSK + ks + tig * 2;
            const int q1 = q0 + 8 * LDSK;
            aH[0] = *reinterpret_cast<const uint32_t*>(&sQh[q0]);
            aH[1] = *reinterpret_cast<const uint32_t*>(&sQh[q1]);
            aH[2] = *reinterpret_cast<const uint32_t*>(&sQh[q0 + 8]);
            aH[3] = *reinterpret_cast<const uint32_t*>(&sQh[q1 + 8]);
            aL[0] = *reinterpret_cast<const uint32_t*>(&sQl[q0]);
            aL[1] = *reinterpret_cast<const uint32_t*>(&sQl[q1]);
            aL[2] = *reinterpret_cast<const uint32_t*>(&sQl[q0 + 8]);
            aL[3] = *reinterpret_cast<const uint32_t*>(&sQl[q1 + 8]);
#pragma unroll
            for (int nf = 0; nf < 16; ++nf) {
                const int r = (nf * 8 + gi) * LDSK + ks + tig * 2;
                uint32_t b[2];
                b[0] = *reinterpret_cast<const uint32_t*>(&sKh[r]);
                b[1] = *reinterpret_cast<const uint32_t*>(&sKh[r + 8]);
                mma16816(s[nf], aH, b);
                mma16816(s[nf], aL, b);
            }
#pragma unroll
            for (int nf = 0; nf < 16; ++nf) {
                const int r = (nf * 8 + gi) * LDSK + ks + tig * 2;
                uint32_t b[2];
                b[0] = *reinterpret_cast<const uint32_t*>(&sKl[r]);
                b[1] = *reinterpret_cast<const uint32_t*>(&sKl[r + 8]);
                mma16816(s[nf], aH, b);
            }
        }

        // online softmax
        float mt0 = -3.4e38f, mt1 = -3.4e38f;
#pragma unroll
        for (int nf = 0; nf < 16; ++nf) {
            mt0 = fmaxf(mt0, fmaxf(s[nf][0], s[nf][1]));
            mt1 = fmaxf(mt1, fmaxf(s[nf][2], s[nf][3]));
        }
        mt0 = fmaxf(mt0, __shfl_xor_sync(0xffffffffu, mt0, 1));
        mt0 = fmaxf(mt0, __shfl_xor_sync(0xffffffffu, mt0, 2));
        mt1 = fmaxf(mt1, __shfl_xor_sync(0xffffffffu, mt1, 1));
        mt1 = fmaxf(mt1, __shfl_xor_sync(0xffffffffu, mt1, 2));
        const float mn0 = fmaxf(m_run0, mt0);
        const float mn1 = fmaxf(m_run1, mt1);
        const float sc0 = __expf(m_run0 - mn0);
        const float sc1 = __expf(m_run1 - mn1);

        uint32_t pH[8][4], pL[8][4];
        float ps0 = 0.f, ps1 = 0.f;
#pragma unroll
        for (int kc = 0; kc < 8; ++kc) {
            const int nf0 = 2 * kc, nf1 = 2 * kc + 1;
            const float p00 = __expf(s[nf0][0] - mn0), p01 = __expf(s[nf0][1] - mn0);
            const float p02 = __expf(s[nf0][2] - mn1), p03 = __expf(s[nf0][3] - mn1);
            const float p10 = __expf(s[nf1][0] - mn0), p11 = __expf(s[nf1][1] - mn0);
            const float p12 = __expf(s[nf1][2] - mn1), p13 = __expf(s[nf1][3] - mn1);
            ps0 += p00 + p01 + p10 + p11;
            ps1 += p02 + p03 + p12 + p13;
            pack_hilo(p00, p01, pH[kc][0], pL[kc][0]);
            pack_hilo(p02, p03, pH[kc][1], pL[kc][1]);
            pack_hilo(p10, p11, pH[kc][2], pL[kc][2]);
            pack_hilo(p12, p13, pH[kc][3], pL[kc][3]);
        }
        ps0 += __shfl_xor_sync(0xffffffffu, ps0, 1);
        ps0 += __shfl_xor_sync(0xffffffffu, ps0, 2);
        ps1 += __shfl_xor_sync(0xffffffffu, ps1, 1);
        ps1 += __shfl_xor_sync(0xffffffffu, ps1, 2);
        l_run0 = l_run0 * sc0 + ps0;
        l_run1 = l_run1 * sc1 + ps1;
        m_run0 = mn0;
        m_run1 = mn1;
#pragma unroll
        for (int nf = 0; nf < 9; ++nf) {
            o[nf][0] *= sc0; o[nf][1] *= sc0;
            o[nf][2] *= sc1; o[nf][3] *= sc1;
        }

        CP_WAIT(0);        // V(kt) arrived
        __syncthreads();   // V visible; sK free (all warps past S-MMA)

        if (kt + 1 < Nn / 128) issueK2(kt + 1);   // K(kt+1) streams during PV

        // O += P V, 3-pass
#pragma unroll
        for (int kc = 0; kc < 8; ++kc) {
#pragma unroll
            for (int nf = 0; nf < 9; ++nf) {
                const int r = (nf * 8 + gi) * LDSV + kc * 16 + tig * 2;
                uint32_t b[2];
                b[0] = *reinterpret_cast<const uint32_t*>(&sVh[r]);
                b[1] = *reinterpret_cast<const uint32_t*>(&sVh[r + 8]);
                mma16816(o[nf], pH[kc], b);
                mma16816(o[nf], pL[kc], b);
                b[0] = *reinterpret_cast<const uint32_t*>(&sVl[r]);
                b[1] = *reinterpret_cast<const uint32_t*>(&sVl[r + 8]);
                mma16816(o[nf], pH[kc], b);
            }
        }
    }

    // epilogue
    const float inv0 = 1.0f / l_run0;
    const float inv1 = 1.0f / l_run1;
    const int b = bh >> 4;
    const int h = bh & 15;
    const int tok0 = m0 + wm + gi;
#pragma unroll
    for (int nf = 0; nf < 9; ++nf) {
        const int col = nf * 8 + tig * 2;
        const size_t o0 = ((size_t)(b * Nn + tok0)) * HID + h * Dd + col;
        const size_t o1 = ((size_t)(b * Nn + tok0 + 8)) * HID + h * Dd + col;
        const float x0 = o[nf][0] * inv0, y0 = o[nf][1] * inv0;
        const float x1 = o[nf][2] * inv1, y1 = o[nf][3] * inv1;
        *reinterpret_cast<__nv_bfloat162*>(&g_oa_hi[o0]) = hilo2(x0, y0, false);
        *reinterpret_cast<__nv_bfloat162*>(&g_oa_lo[o0]) = hilo2(x0, y0, true);
        *reinterpret_cast<__nv_bfloat162*>(&g_oa_hi[o1]) = hilo2(x1, y1, false);
        *reinterpret_cast<__nv_bfloat162*>(&g_oa_lo[o1]) = hilo2(x1, y1, true);
    }
}

// ---------------------------------------------------------------------------
extern "C" void kernel_launch(void* const* d_in, const int* in_sizes, int n_in,
                              void* d_out, int out_size) {
    const float* x     = (const float*)d_in[0];
    const float* w_qkv = (const float*)d_in[1];
    const float* b_qkv = (const float*)d_in[2];
    const float* w_out = (const float*)d_in[3];
    const float* b_out = (const float*)d_in[4];
    float* out = (float*)d_out;

    cudaFuncSetAttribute(k_flash, cudaFuncAttributeMaxDynamicSharedMemorySize, FLASH_SMEM);
    cudaFuncSetAttribute(k_gemm<0>, cudaFuncAttributeMaxDynamicSharedMemorySize, GEMM_SMEM);
    cudaFuncSetAttribute(k_gemm<1>, cudaFuncAttributeMaxDynamicSharedMemorySize, GEMM_SMEM);

    const int n4 = MTOK * HID / 4;

    // prep
    k_zpad<<<(BHEAD * Nn + 255) / 256, 256>>>();
    k_split<<<(n4 + 255) / 256, 256>>>(x);
    k_tsplit<QKVN, 0><<<dim3(QKVN / 32, HID / 32), dim3(32, 8)>>>(w_qkv);
    k_tsplit<HID, 1><<<dim3(HID / 32, HID / 32), dim3(32, 8)>>>(w_out);

    // 1. QKV projection -> Q(scaled)/K hi/lo (padded), V^T hi/lo
    k_gemm<0><<<dim3(QKVN / 128, MTOK / 128), 256, GEMM_SMEM>>>(b_qkv, nullptr);

    // 2. fused flash attention -> g_oa hi/lo
    k_flash<<<dim3(Nn / 128, BHEAD), 256, FLASH_SMEM>>>();

    // 3. output projection
    k_gemm<1><<<dim3(HID / 128, MTOK / 128), 256, GEMM_SMEM>>>(b_out, out);
}

// round 7
// speedup vs baseline: 3.9513x; 1.0501x over previous
#include <cuda_runtime.h>
#include <cuda_bf16.h>
#include <cstdint>

// ---------------------------------------------------------------------------
// Attention_21474836480706: B=4, N=1024, H=16, D=72, HID=1152 (fp32)
// R7: R6 + ldmatrix fragment loads everywhere (A via x4, B/K/V via paired x4).
// Math identical (hi/lo bf16 3-pass).
// ---------------------------------------------------------------------------

namespace {
constexpr int Bb    = 4;
constexpr int Nn    = 1024;
constexpr int Hh    = 16;
constexpr int Dd    = 72;
constexpr int DP    = 80;
constexpr int HID   = 1152;
constexpr int ATT   = Hh * Dd;        // 1152
constexpr int MTOK  = Bb * Nn;        // 4096
constexpr int QKVN  = 3 * ATT;        // 3456
constexpr int BHEAD = Bb * Hh;        // 64
}

// ------------------------------ scratch ------------------------------------
__device__ __align__(16) __nv_bfloat16 g_qh[(size_t)BHEAD * Nn * DP];   // Q pre-scaled
__device__ __align__(16) __nv_bfloat16 g_ql[(size_t)BHEAD * Nn * DP];
__device__ __align__(16) __nv_bfloat16 g_kh[(size_t)BHEAD * Nn * DP];
__device__ __align__(16) __nv_bfloat16 g_kl[(size_t)BHEAD * Nn * DP];
__device__ __align__(16) __nv_bfloat16 g_vth[(size_t)BHEAD * Dd * Nn];  // V^T [bh][d][tok]
__device__ __align__(16) __nv_bfloat16 g_vtl[(size_t)BHEAD * Dd * Nn];

__device__ __align__(16) __nv_bfloat16 g_xa_hi[(size_t)MTOK * HID];
__device__ __align__(16) __nv_bfloat16 g_xa_lo[(size_t)MTOK * HID];
__device__ __align__(16) __nv_bfloat16 g_oa_hi[(size_t)MTOK * HID];
__device__ __align__(16) __nv_bfloat16 g_oa_lo[(size_t)MTOK * HID];
__device__ __align__(16) __nv_bfloat16 g_wqkvt_hi[(size_t)QKVN * HID];
__device__ __align__(16) __nv_bfloat16 g_wqkvt_lo[(size_t)QKVN * HID];
__device__ __align__(16) __nv_bfloat16 g_wot_hi[(size_t)HID * HID];
__device__ __align__(16) __nv_bfloat16 g_wot_lo[(size_t)HID * HID];

// --------------------------- helpers ---------------------------------------
__device__ __forceinline__ uint32_t smem_u32(const void* p) {
    uint32_t a;
    asm("{ .reg .u64 t; cvta.to.shared.u64 t, %1; cvt.u32.u64 %0, t; }" : "=r"(a) : "l"(p));
    return a;
}
__device__ __forceinline__ void cp16(uint32_t s, const void* g) {
    asm volatile("cp.async.cg.shared.global [%0], [%1], 16;" :: "r"(s), "l"(g));
}
#define CP_COMMIT() asm volatile("cp.async.commit_group;" ::: "memory")
#define CP_WAIT(n)  asm volatile("cp.async.wait_group %0;" :: "n"(n) : "memory")

__device__ __forceinline__ void ldsm4(uint32_t& r0, uint32_t& r1, uint32_t& r2, uint32_t& r3,
                                      uint32_t a) {
    asm volatile("ldmatrix.sync.aligned.m8n8.x4.shared.b16 {%0,%1,%2,%3}, [%4];"
                 : "=r"(r0), "=r"(r1), "=r"(r2), "=r"(r3) : "r"(a));
}
__device__ __forceinline__ void ldsm2(uint32_t& r0, uint32_t& r1, uint32_t a) {
    asm volatile("ldmatrix.sync.aligned.m8n8.x2.shared.b16 {%0,%1}, [%2];"
                 : "=r"(r0), "=r"(r1) : "r"(a));
}
__device__ __forceinline__ void mma16816(float* d, const uint32_t* a, const uint32_t* b) {
    asm volatile(
        "mma.sync.aligned.m16n8k16.row.col.f32.bf16.bf16.f32 "
        "{%0,%1,%2,%3}, {%4,%5,%6,%7}, {%8,%9}, {%0,%1,%2,%3};"
        : "+f"(d[0]), "+f"(d[1]), "+f"(d[2]), "+f"(d[3])
        : "r"(a[0]), "r"(a[1]), "r"(a[2]), "r"(a[3]), "r"(b[0]), "r"(b[1]));
}
__device__ __forceinline__ __nv_bfloat162 hilo2(float a, float b, bool lo) {
    __nv_bfloat16 ha = __float2bfloat16(a), hb = __float2bfloat16(b);
    if (!lo) return __halves2bfloat162(ha, hb);
    return __halves2bfloat162(__float2bfloat16(a - __bfloat162float(ha)),
                              __float2bfloat16(b - __bfloat162float(hb)));
}
__device__ __forceinline__ void pack_hilo(float a, float b, uint32_t& hi, uint32_t& lo) {
    __nv_bfloat16 ha = __float2bfloat16(a), hb = __float2bfloat16(b);
    __nv_bfloat162 h2 = __halves2bfloat162(ha, hb);
    __nv_bfloat162 l2 = __halves2bfloat162(__float2bfloat16(a - __bfloat162float(ha)),
                                           __float2bfloat16(b - __bfloat162float(hb)));
    hi = *reinterpret_cast<uint32_t*>(&h2);
    lo = *reinterpret_cast<uint32_t*>(&l2);
}

// ---------------------------------------------------------------------------
__global__ __launch_bounds__(256) void k_zpad() {
    const int i = blockIdx.x * 256 + threadIdx.x;
    if (i >= BHEAD * Nn) return;
    const size_t o = (size_t)i * DP + Dd;
    const uint4 z = make_uint4(0, 0, 0, 0);
    *reinterpret_cast<uint4*>(&g_qh[o]) = z;
    *reinterpret_cast<uint4*>(&g_ql[o]) = z;
    *reinterpret_cast<uint4*>(&g_kh[o]) = z;
    *reinterpret_cast<uint4*>(&g_kl[o]) = z;
}

__global__ __launch_bounds__(256) void k_split(const float* __restrict__ in) {
    const int n4 = MTOK * HID / 4;
    int i = blockIdx.x * 256 + threadIdx.x;
    if (i >= n4) return;
    float4 v = reinterpret_cast<const float4*>(in)[i];
    reinterpret_cast<__nv_bfloat162*>(g_xa_hi)[2 * i]     = hilo2(v.x, v.y, false);
    reinterpret_cast<__nv_bfloat162*>(g_xa_hi)[2 * i + 1] = hilo2(v.z, v.w, false);
    reinterpret_cast<__nv_bfloat162*>(g_xa_lo)[2 * i]     = hilo2(v.x, v.y, true);
    reinterpret_cast<__nv_bfloat162*>(g_xa_lo)[2 * i + 1] = hilo2(v.z, v.w, true);
}

template <int NCOLS, int WHICH>
__global__ void k_tsplit(const float* __restrict__ W) {
    __shared__ float t[32][33];
    const int n0 = blockIdx.x * 32, k0 = blockIdx.y * 32;
    const int tx = threadIdx.x, ty = threadIdx.y;   // (32, 8)
#pragma unroll
    for (int i = 0; i < 4; ++i)
        t[ty * 4 + i][tx] = W[(size_t)(k0 + ty * 4 + i) * NCOLS + n0 + tx];
    __syncthreads();
    __nv_bfloat16* Hi = WHICH ? g_wot_hi : g_wqkvt_hi;
    __nv_bfloat16* Lo = WHICH ? g_wot_lo : g_wqkvt_lo;
#pragma unroll
    for (int i = 0; i < 4; ++i) {
        float v = t[tx][ty * 4 + i];
        __nv_bfloat16 h = __float2bfloat16(v);
        __nv_bfloat16 l = __float2bfloat16(v - __bfloat162float(h));
        size_t o = (size_t)(n0 + ty * 4 + i) * HID + k0 + tx;
        Hi[o] = h;
        Lo[o] = l;
    }
}

// ---------------------------------------------------------------------------
// HMMA GEMM (projections), 2-stage cp.async + ldmatrix.
// ---------------------------------------------------------------------------
namespace {
constexpr int GBM = 128, GBK = 32, GLDS = 40;
constexpr int GTILE = GBM * GLDS;
constexpr int GSTAGE = 4 * GTILE;
constexpr int GEMM_SMEM = 2 * GSTAGE * 2;         // 81920 B
}

template <int MODE>
__global__ __launch_bounds__(256) void k_gemm(const float* __restrict__ bias,
                                              float* __restrict__ Cout) {
    extern __shared__ __nv_bfloat16 gsm[];

    const int tid  = threadIdx.x;
    const int warp = tid >> 5, lane = tid & 31;
    const int wm = (warp >> 2) * 64;
    const int wn = (warp & 3) * 32;
    const int gi  = lane >> 2;
    const int tig = lane & 3;
    const int m0 = blockIdx.y * GBM;
    const int n0 = blockIdx.x * GBM;

    // ldmatrix per-lane geometry
    const int lane7 = lane & 7;
    const int aRow = lane7 + ((lane & 8) ? 8 : 0);    // A x4: row within 16
    const int aK   = (lane & 16) ? 8 : 0;             // A x4: k-half
    const int bRow = lane7 + ((lane & 16) ? 8 : 0);   // B paired-x4: row within 16
    const int bK   = (lane & 8) ? 8 : 0;              // B: k-half

    const __nv_bfloat16* __restrict__ Ah = MODE ? g_oa_hi : g_xa_hi;
    const __nv_bfloat16* __restrict__ Al = MODE ? g_oa_lo : g_xa_lo;
    const __nv_bfloat16* __restrict__ Bh = MODE ? g_wot_hi : g_wqkvt_hi;
    const __nv_bfloat16* __restrict__ Bl = MODE ? g_wot_lo : g_wqkvt_lo;

    const int r0c = tid >> 2, k0c = (tid & 3);
    const int r1c = (tid + 256) >> 2, k1c = (tid & 3);

    auto issue_tile = [&](int kt, int stage) {
        __nv_bfloat16* base = gsm + stage * GSTAGE;
        const int kk = kt * GBK;
#pragma unroll
        for (int c = 0; c < 2; ++c) {
            const int row = c ? r1c : r0c;
            const int kc  = c ? k1c : k0c;
            const uint32_t soff = smem_u32(base + row * GLDS + kc * 8);
            const size_t ga = (size_t)(m0 + row) * HID + kk + kc * 8;
            const size_t gb = (size_t)(n0 + row) * HID + kk + kc * 8;
            cp16(soff,                 Ah + ga);
            cp16(soff + GTILE * 2,     Al + ga);
            cp16(soff + 2 * GTILE * 2, Bh + gb);
            cp16(soff + 3 * GTILE * 2, Bl + gb);
        }
        CP_COMMIT();
    };

    float acc[4][4][4] = {};
    constexpr int NT = HID / GBK;   // 36

    issue_tile(0, 0);

    for (int t = 0; t < NT; ++t) {
        if (t + 1 < NT) {
            issue_tile(t + 1, (t + 1) & 1);
            CP_WAIT(1);
        } else {
            CP_WAIT(0);
        }
        __syncthreads();

        const uint32_t uAh = smem_u32(gsm + (t & 1) * GSTAGE);
        const uint32_t uAl = uAh + GTILE * 2;
        const uint32_t uBh = uAh + 2 * GTILE * 2;
        const uint32_t uBl = uAh + 3 * GTILE * 2;

#pragma unroll
        for (int ks = 0; ks < GBK; ks += 16) {
            uint32_t ah[4][4], al[4][4], b[4][2];
#pragma unroll
            for (int mf = 0; mf < 4; ++mf) {
                const uint32_t off = ((wm + mf * 16 + aRow) * GLDS + ks + aK) * 2;
                ldsm4(ah[mf][0], ah[mf][1], ah[mf][2], ah[mf][3], uAh + off);
                ldsm4(al[mf][0], al[mf][1], al[mf][2], al[mf][3], uAl + off);
            }
#pragma unroll
            for (int np = 0; np < 2; ++np) {   // pairs of n-frags
                const uint32_t off = ((wn + np * 16 + bRow) * GLDS + ks + bK) * 2;
                ldsm4(b[2 * np][0], b[2 * np][1], b[2 * np + 1][0], b[2 * np + 1][1], uBh + off);
            }
#pragma unroll
            for (int mf = 0; mf < 4; ++mf)
#pragma unroll
                for (int nf = 0; nf < 4; ++nf) {
                    mma16816(acc[mf][nf], ah[mf], b[nf]);
                    mma16816(acc[mf][nf], al[mf], b[nf]);
                }
#pragma unroll
            for (int np = 0; np < 2; ++np) {
                const uint32_t off = ((wn + np * 16 + bRow) * GLDS + ks + bK) * 2;
                ldsm4(b[2 * np][0], b[2 * np][1], b[2 * np + 1][0], b[2 * np + 1][1], uBl + off);
            }
#pragma unroll
            for (int mf = 0; mf < 4; ++mf)
#pragma unroll
                for (int nf = 0; nf < 4; ++nf)
                    mma16816(acc[mf][nf], ah[mf], b[nf]);
        }
        __syncthreads();
    }

    const float qscale = 0.11785113019775793f;  // 1/sqrt(72)
#pragma unroll
    for (int mf = 0; mf < 4; ++mf) {
#pragma unroll
        for (int nf = 0; nf < 4; ++nf) {
            const int row = m0 + wm + mf * 16 + gi;
            const int col = n0 + wn + nf * 8 + tig * 2;
            const float b0 = bias[col], b1 = bias[col + 1];
            float x0 = acc[mf][nf][0] + b0, y0 = acc[mf][nf][1] + b1;
            float x1 = acc[mf][nf][2] + b0, y1 = acc[mf][nf][3] + b1;
            if (MODE == 0) {
                const int which = n0 / ATT;
                const int rem = col - which * ATT;
                const int h = rem / Dd, d = rem - h * Dd;
                const int bb = row >> 10, tok = row & 1023;
                const int bh = bb * Hh + h;
                if (which < 2) {
                    if (which == 0) { x0 *= qscale; y0 *= qscale; x1 *= qscale; y1 *= qscale; }
                    __nv_bfloat16* Hi = which ? g_kh : g_qh;
                    __nv_bfloat16* Lo = which ? g_kl : g_ql;
                    const size_t o0 = ((size_t)bh * Nn + tok) * DP + d;
                    const size_t o1 = o0 + 8 * DP;
                    *reinterpret_cast<__nv_bfloat162*>(&Hi[o0]) = hilo2(x0, y0, false);
                    *reinterpret_cast<__nv_bfloat162*>(&Lo[o0]) = hilo2(x0, y0, true);
                    *reinterpret_cast<__nv_bfloat162*>(&Hi[o1]) = hilo2(x1, y1, false);
                    *reinterpret_cast<__nv_bfloat162*>(&Lo[o1]) = hilo2(x1, y1, true);
                } else {
                    const size_t b0o = ((size_t)bh * Dd + d) * Nn + tok;
                    const size_t b1o = b0o + Nn;
                    __nv_bfloat16 h0 = __float2bfloat16(x0);
                    __nv_bfloat16 h1 = __float2bfloat16(y0);
                    __nv_bfloat16 h2 = __float2bfloat16(x1);
                    __nv_bfloat16 h3 = __float2bfloat16(y1);
                    g_vth[b0o]     = h0;
                    g_vth[b1o]     = h1;
                    g_vth[b0o + 8] = h2;
                    g_vth[b1o + 8] = h3;
                    g_vtl[b0o]     = __float2bfloat16(x0 - __bfloat162float(h0));
                    g_vtl[b1o]     = __float2bfloat16(y0 - __bfloat162float(h1));
                    g_vtl[b0o + 8] = __float2bfloat16(x1 - __bfloat162float(h2));
                    g_vtl[b1o + 8] = __float2bfloat16(y1 - __bfloat162float(h3));
                }
            } else {
                *reinterpret_cast<float2*>(&Cout[(size_t)row * HID + col]) = make_float2(x0, y0);
                *reinterpret_cast<float2*>(&Cout[(size_t)(row + 8) * HID + col]) = make_float2(x1, y1);
            }
        }
    }
}

// ---------------------------------------------------------------------------
// Flash attention: cp.async overlap + ldmatrix fragment loads.
// ---------------------------------------------------------------------------
namespace {
constexpr int LDSK = 88;
constexpr int LDSV = 136;
constexpr int QELE = 128 * LDSK;
constexpr int VELE = Dd * LDSV;
constexpr int FLASH_SMEM = (4 * QELE + 2 * VELE) * 2;   // 129280 B
}

__global__ __launch_bounds__(256) void k_flash() {
    extern __shared__ __nv_bfloat16 sm[];
    __nv_bfloat16* sQh = sm;
    __nv_bfloat16* sQl = sm + QELE;
    __nv_bfloat16* sKh = sm + 2 * QELE;
    __nv_bfloat16* sKl = sm + 3 * QELE;
    __nv_bfloat16* sVh = sm + 4 * QELE;
    __nv_bfloat16* sVl = sm + 4 * QELE + VELE;

    const int tid  = threadIdx.x;
    const int warp = tid >> 5, lane = tid & 31;
    const int wm  = warp * 16;
    const int gi  = lane >> 2;
    const int tig = lane & 3;
    const int bh = blockIdx.y;
    const int m0 = blockIdx.x * 128;

    const int lane7 = lane & 7;
    const int aRow = lane7 + ((lane & 8) ? 8 : 0);
    const int aK   = (lane & 16) ? 8 : 0;
    const int bRow = lane7 + ((lane & 16) ? 8 : 0);
    const int bK   = (lane & 8) ? 8 : 0;

    const uint32_t uQh = smem_u32(sQh), uQl = smem_u32(sQl);
    const uint32_t uKh = smem_u32(sKh), uKl = smem_u32(sKl);
    const uint32_t uVh = smem_u32(sVh), uVl = smem_u32(sVl);

    const __nv_bfloat16* __restrict__ Qh = g_qh + (size_t)bh * Nn * DP;
    const __nv_bfloat16* __restrict__ Ql = g_ql + (size_t)bh * Nn * DP;
    const __nv_bfloat16* __restrict__ Kh = g_kh + (size_t)bh * Nn * DP;
    const __nv_bfloat16* __restrict__ Kl = g_kl + (size_t)bh * Nn * DP;
    const __nv_bfloat16* __restrict__ Vh = g_vth + (size_t)bh * Dd * Nn;
    const __nv_bfloat16* __restrict__ Vl = g_vtl + (size_t)bh * Dd * Nn;

    auto issueK = [&](int kt) {
        const int nn = kt * 128;
#pragma unroll
        for (int c = 0; c < 5; ++c) {
            const int chunk = tid + c * 256;
            const int row = chunk / 10;
            const int kc  = chunk - row * 10;
            const size_t gk = (size_t)(nn + row) * DP + kc * 8;
            cp16(smem_u32(sKh + row * LDSK + kc * 8), Kh + gk);
            cp16(smem_u32(sKl + row * LDSK + kc * 8), Kl + gk);
        }
        CP_COMMIT();
    };
    auto issueV = [&](int kt) {
        const int nn = kt * 128;
        for (int idx = tid; idx < Dd * 16; idx += 256) {
            const int row = idx >> 4;
            const int kc  = idx & 15;
            const size_t gv = (size_t)row * Nn + nn + kc * 8;
            cp16(smem_u32(sVh + row * LDSV + kc * 8), Vh + gv);
            cp16(smem_u32(sVl + row * LDSV + kc * 8), Vl + gv);
        }
        CP_COMMIT();
    };

    issueK(0);
#pragma unroll
    for (int c = 0; c < 5; ++c) {
        const int chunk = tid + c * 256;
        const int row = chunk / 10;
        const int kc  = chunk - row * 10;
        const int soff = row * LDSK + kc * 8;
        const size_t gq = (size_t)(m0 + row) * DP + kc * 8;
        *reinterpret_cast<uint4*>(&sQh[soff]) = *reinterpret_cast<const uint4*>(&Qh[gq]);
        *reinterpret_cast<uint4*>(&sQl[soff]) = *reinterpret_cast<const uint4*>(&Ql[gq]);
    }

    float m_run0 = -3.4e38f, m_run1 = -3.4e38f;
    float l_run0 = 0.f, l_run1 = 0.f;
    float o[9][4] = {};

    for (int kt = 0; kt < Nn / 128; ++kt) {
        CP_WAIT(0);
        __syncthreads();

        issueV(kt);

        // S = Q K^T, 3-pass, ldmatrix
        float s[16][4];
#pragma unroll
        for (int nf = 0; nf < 16; ++nf)
            s[nf][0] = s[nf][1] = s[nf][2] = s[nf][3] = 0.f;
#pragma unroll
        for (int ks = 0; ks < DP; ks += 16) {
            uint32_t aH[4], aL[4], b[2][2];
            const uint32_t aoff = ((wm + aRow) * LDSK + ks + aK) * 2;
            ldsm4(aH[0], aH[1], aH[2], aH[3], uQh + aoff);
            ldsm4(aL[0], aL[1], aL[2], aL[3], uQl + aoff);
#pragma unroll
            for (int np = 0; np < 8; ++np) {
                const uint32_t boff = ((np * 16 + bRow) * LDSK + ks + bK) * 2;
                ldsm4(b[0][0], b[0][1], b[1][0], b[1][1], uKh + boff);
                mma16816(s[2 * np],     aH, b[0]);
                mma16816(s[2 * np],     aL, b[0]);
                mma16816(s[2 * np + 1], aH, b[1]);
                mma16816(s[2 * np + 1], aL, b[1]);
            }
#pragma unroll
            for (int np = 0; np < 8; ++np) {
                const uint32_t boff = ((np * 16 + bRow) * LDSK + ks + bK) * 2;
                ldsm4(b[0][0], b[0][1], b[1][0], b[1][1], uKl + boff);
                mma16816(s[2 * np],     aH, b[0]);
                mma16816(s[2 * np + 1], aH, b[1]);
            }
        }

        // online softmax
        float mt0 = -3.4e38f, mt1 = -3.4e38f;
#pragma unroll
        for (int nf = 0; nf < 16; ++nf) {
            mt0 = fmaxf(mt0, fmaxf(s[nf][0], s[nf][1]));
            mt1 = fmaxf(mt1, fmaxf(s[nf][2], s[nf][3]));
        }
        mt0 = fmaxf(mt0, __shfl_xor_sync(0xffffffffu, mt0, 1));
        mt0 = fmaxf(mt0, __shfl_xor_sync(0xffffffffu, mt0, 2));
        mt1 = fmaxf(mt1, __shfl_xor_sync(0xffffffffu, mt1, 1));
        mt1 = fmaxf(mt1, __shfl_xor_sync(0xffffffffu, mt1, 2));
        const float mn0 = fmaxf(m_run0, mt0);
        const float mn1 = fmaxf(m_run1, mt1);
        const float sc0 = __expf(m_run0 - mn0);
        const float sc1 = __expf(m_run1 - mn1);

        uint32_t pH[8][4], pL[8][4];
        float ps0 = 0.f, ps1 = 0.f;
#pragma unroll
        for (int kc = 0; kc < 8; ++kc) {
            const int nf0 = 2 * kc, nf1 = 2 * kc + 1;
            const float p00 = __expf(s[nf0][0] - mn0), p01 = __expf(s[nf0][1] - mn0);
            const float p02 = __expf(s[nf0][2] - mn1), p03 = __expf(s[nf0][3] - mn1);
            const float p10 = __expf(s[nf1][0] - mn0), p11 = __expf(s[nf1][1] - mn0);
            const float p12 = __expf(s[nf1][2] - mn1), p13 = __expf(s[nf1][3] - mn1);
            ps0 += p00 + p01 + p10 + p11;
            ps1 += p02 + p03 + p12 + p13;
            pack_hilo(p00, p01, pH[kc][0], pL[kc][0]);
            pack_hilo(p02, p03, pH[kc][1], pL[kc][1]);
            pack_hilo(p10, p11, pH[kc][2], pL[kc][2]);
            pack_hilo(p12, p13, pH[kc][3], pL[kc][3]);
        }
        ps0 += __shfl_xor_sync(0xffffffffu, ps0, 1);
        ps0 += __shfl_xor_sync(0xffffffffu, ps0, 2);
        ps1 += __shfl_xor_sync(0xffffffffu, ps1, 1);
        ps1 += __shfl_xor_sync(0xffffffffu, ps1, 2);
        l_run0 = l_run0 * sc0 + ps0;
        l_run1 = l_run1 * sc1 + ps1;
        m_run0 = mn0;
        m_run1 = mn1;
#pragma unroll
        for (int nf = 0; nf < 9; ++nf) {
            o[nf][0] *= sc0; o[nf][1] *= sc0;
            o[nf][2] *= sc1; o[nf][3] *= sc1;
        }

        CP_WAIT(0);
        __syncthreads();

        if (kt + 1 < Nn / 128) issueK(kt + 1);

        // O += P V, 3-pass, ldmatrix (9 n-frags: 4 pairs + 1 single)
#pragma unroll
        for (int kc = 0; kc < 8; ++kc) {
            uint32_t b[9][2];
#pragma unroll
            for (int np = 0; np < 4; ++np) {
                const uint32_t off = ((np * 16 + bRow) * LDSV + kc * 16 + bK) * 2;
                ldsm4(b[2 * np][0], b[2 * np][1], b[2 * np + 1][0], b[2 * np + 1][1], uVh + off);
            }
            {
                const uint32_t off = ((64 + lane7) * LDSV + kc * 16 + bK) * 2;
                ldsm2(b[8][0], b[8][1], uVh + off);
            }
#pragma unroll
            for (int nf = 0; nf < 9; ++nf) {
                mma16816(o[nf], pH[kc], b[nf]);
                mma16816(o[nf], pL[kc], b[nf]);
            }
#pragma unroll
            for (int np = 0; np < 4; ++np) {
                const uint32_t off = ((np * 16 + bRow) * LDSV + kc * 16 + bK) * 2;
                ldsm4(b[2 * np][0], b[2 * np][1], b[2 * np + 1][0], b[2 * np + 1][1], uVl + off);
            }
            {
                const uint32_t off = ((64 + lane7) * LDSV + kc * 16 + bK) * 2;
                ldsm2(b[8][0], b[8][1], uVl + off);
            }
#pragma unroll
            for (int nf = 0; nf < 9; ++nf)
                mma16816(o[nf], pH[kc], b[nf]);
        }
    }

    // epilogue
    const float inv0 = 1.0f / l_run0;
    const float inv1 = 1.0f / l_run1;
    const int b = bh >> 4;
    const int h = bh & 15;
    const int tok0 = m0 + wm + gi;
#pragma unroll
    for (int nf = 0; nf < 9; ++nf) {
        const int col = nf * 8 + tig * 2;
        const size_t o0 = ((size_t)(b * Nn + tok0)) * HID + h * Dd + col;
        const size_t o1 = ((size_t)(b * Nn + tok0 + 8)) * HID + h * Dd + col;
        const float x0 = o[nf][0] * inv0, y0 = o[nf][1] * inv0;
        const float x1 = o[nf][2] * inv1, y1 = o[nf][3] * inv1;
        *reinterpret_cast<__nv_bfloat162*>(&g_oa_hi[o0]) = hilo2(x0, y0, false);
        *reinterpret_cast<__nv_bfloat162*>(&g_oa_lo[o0]) = hilo2(x0, y0, true);
        *reinterpret_cast<__nv_bfloat162*>(&g_oa_hi[o1]) = hilo2(x1, y1, false);
        *reinterpret_cast<__nv_bfloat162*>(&g_oa_lo[o1]) = hilo2(x1, y1, true);
    }
}

// ---------------------------------------------------------------------------
extern "C" void kernel_launch(void* const* d_in, const int* in_sizes, int n_in,
                              void* d_out, int out_size) {
    const float* x     = (const float*)d_in[0];
    const float* w_qkv = (const float*)d_in[1];
    const float* b_qkv = (const float*)d_in[2];
    const float* w_out = (const float*)d_in[3];
    const float* b_out = (const float*)d_in[4];
    float* out = (float*)d_out;

    cudaFuncSetAttribute(k_flash, cudaFuncAttributeMaxDynamicSharedMemorySize, FLASH_SMEM);
    cudaFuncSetAttribute(k_gemm<0>, cudaFuncAttributeMaxDynamicSharedMemorySize, GEMM_SMEM);
    cudaFuncSetAttribute(k_gemm<1>, cudaFuncAttributeMaxDynamicSharedMemorySize, GEMM_SMEM);

    const int n4 = MTOK * HID / 4;

    // prep
    k_zpad<<<(BHEAD * Nn + 255) / 256, 256>>>();
    k_split<<<(n4 + 255) / 256, 256>>>(x);
    k_tsplit<QKVN, 0><<<dim3(QKVN / 32, HID / 32), dim3(32, 8)>>>(w_qkv);
    k_tsplit<HID, 1><<<dim3(HID / 32, HID / 32), dim3(32, 8)>>>(w_out);

    // 1. QKV projection -> Q(scaled)/K hi/lo (padded), V^T hi/lo
    k_gemm<0><<<dim3(QKVN / 128, MTOK / 128), 256, GEMM_SMEM>>>(b_qkv, nullptr);

    // 2. fused flash attention -> g_oa hi/lo
    k_flash<<<dim3(Nn / 128, BHEAD), 256, FLASH_SMEM>>>();

    // 3. output projection
    k_gemm<1><<<dim3(HID / 128, MTOK / 128), 256, GEMM_SMEM>>>(b_out, out);
}

// round 8
// speedup vs baseline: 4.2037x; 1.0639x over previous
#include <cuda_runtime.h>
#include <cuda_bf16.h>
#include <cstdint>

// ---------------------------------------------------------------------------
// Attention_21474836480706: B=4, N=1024, H=16, D=72, HID=1152 (fp32)
// R8: flash reworked for 2 CTAs/SM (64-token K/V tiles, 86KB smem) with
// exp/pack/PV interleaved per k-chunk. Projections unchanged from R7.
// ---------------------------------------------------------------------------

namespace {
constexpr int Bb    = 4;
constexpr int Nn    = 1024;
constexpr int Hh    = 16;
constexpr int Dd    = 72;
constexpr int DP    = 80;
constexpr int HID   = 1152;
constexpr int ATT   = Hh * Dd;        // 1152
constexpr int MTOK  = Bb * Nn;        // 4096
constexpr int QKVN  = 3 * ATT;        // 3456
constexpr int BHEAD = Bb * Hh;        // 64
}

// ------------------------------ scratch ------------------------------------
__device__ __align__(16) __nv_bfloat16 g_qh[(size_t)BHEAD * Nn * DP];   // Q pre-scaled
__device__ __align__(16) __nv_bfloat16 g_ql[(size_t)BHEAD * Nn * DP];
__device__ __align__(16) __nv_bfloat16 g_kh[(size_t)BHEAD * Nn * DP];
__device__ __align__(16) __nv_bfloat16 g_kl[(size_t)BHEAD * Nn * DP];
__device__ __align__(16) __nv_bfloat16 g_vth[(size_t)BHEAD * Dd * Nn];  // V^T [bh][d][tok]
__device__ __align__(16) __nv_bfloat16 g_vtl[(size_t)BHEAD * Dd * Nn];

__device__ __align__(16) __nv_bfloat16 g_xa_hi[(size_t)MTOK * HID];
__device__ __align__(16) __nv_bfloat16 g_xa_lo[(size_t)MTOK * HID];
__device__ __align__(16) __nv_bfloat16 g_oa_hi[(size_t)MTOK * HID];
__device__ __align__(16) __nv_bfloat16 g_oa_lo[(size_t)MTOK * HID];
__device__ __align__(16) __nv_bfloat16 g_wqkvt_hi[(size_t)QKVN * HID];
__device__ __align__(16) __nv_bfloat16 g_wqkvt_lo[(size_t)QKVN * HID];
__device__ __align__(16) __nv_bfloat16 g_wot_hi[(size_t)HID * HID];
__device__ __align__(16) __nv_bfloat16 g_wot_lo[(size_t)HID * HID];

// --------------------------- helpers ---------------------------------------
__device__ __forceinline__ uint32_t smem_u32(const void* p) {
    uint32_t a;
    asm("{ .reg .u64 t; cvta.to.shared.u64 t, %1; cvt.u32.u64 %0, t; }" : "=r"(a) : "l"(p));
    return a;
}
__device__ __forceinline__ void cp16(uint32_t s, const void* g) {
    asm volatile("cp.async.cg.shared.global [%0], [%1], 16;" :: "r"(s), "l"(g));
}
#define CP_COMMIT() asm volatile("cp.async.commit_group;" ::: "memory")
#define CP_WAIT(n)  asm volatile("cp.async.wait_group %0;" :: "n"(n) : "memory")

__device__ __forceinline__ void ldsm4(uint32_t& r0, uint32_t& r1, uint32_t& r2, uint32_t& r3,
                                      uint32_t a) {
    asm volatile("ldmatrix.sync.aligned.m8n8.x4.shared.b16 {%0,%1,%2,%3}, [%4];"
                 : "=r"(r0), "=r"(r1), "=r"(r2), "=r"(r3) : "r"(a));
}
__device__ __forceinline__ void ldsm2(uint32_t& r0, uint32_t& r1, uint32_t a) {
    asm volatile("ldmatrix.sync.aligned.m8n8.x2.shared.b16 {%0,%1}, [%2];"
                 : "=r"(r0), "=r"(r1) : "r"(a));
}
__device__ __forceinline__ void mma16816(float* d, const uint32_t* a, const uint32_t* b) {
    asm volatile(
        "mma.sync.aligned.m16n8k16.row.col.f32.bf16.bf16.f32 "
        "{%0,%1,%2,%3}, {%4,%5,%6,%7}, {%8,%9}, {%0,%1,%2,%3};"
        : "+f"(d[0]), "+f"(d[1]), "+f"(d[2]), "+f"(d[3])
        : "r"(a[0]), "r"(a[1]), "r"(a[2]), "r"(a[3]), "r"(b[0]), "r"(b[1]));
}
__device__ __forceinline__ __nv_bfloat162 hilo2(float a, float b, bool lo) {
    __nv_bfloat16 ha = __float2bfloat16(a), hb = __float2bfloat16(b);
    if (!lo) return __halves2bfloat162(ha, hb);
    return __halves2bfloat162(__float2bfloat16(a - __bfloat162float(ha)),
                              __float2bfloat16(b - __bfloat162float(hb)));
}
__device__ __forceinline__ void pack_hilo(float a, float b, uint32_t& hi, uint32_t& lo) {
    __nv_bfloat16 ha = __float2bfloat16(a), hb = __float2bfloat16(b);
    __nv_bfloat162 h2 = __halves2bfloat162(ha, hb);
    __nv_bfloat162 l2 = __halves2bfloat162(__float2bfloat16(a - __bfloat162float(ha)),
                                           __float2bfloat16(b - __bfloat162float(hb)));
    hi = *reinterpret_cast<uint32_t*>(&h2);
    lo = *reinterpret_cast<uint32_t*>(&l2);
}

// ---------------------------------------------------------------------------
__global__ __launch_bounds__(256) void k_zpad() {
    const int i = blockIdx.x * 256 + threadIdx.x;
    if (i >= BHEAD * Nn) return;
    const size_t o = (size_t)i * DP + Dd;
    const uint4 z = make_uint4(0, 0, 0, 0);
    *reinterpret_cast<uint4*>(&g_qh[o]) = z;
    *reinterpret_cast<uint4*>(&g_ql[o]) = z;
    *reinterpret_cast<uint4*>(&g_kh[o]) = z;
    *reinterpret_cast<uint4*>(&g_kl[o]) = z;
}

__global__ __launch_bounds__(256) void k_split(const float* __restrict__ in) {
    const int n4 = MTOK * HID / 4;
    int i = blockIdx.x * 256 + threadIdx.x;
    if (i >= n4) return;
    float4 v = reinterpret_cast<const float4*>(in)[i];
    reinterpret_cast<__nv_bfloat162*>(g_xa_hi)[2 * i]     = hilo2(v.x, v.y, false);
    reinterpret_cast<__nv_bfloat162*>(g_xa_hi)[2 * i + 1] = hilo2(v.z, v.w, false);
    reinterpret_cast<__nv_bfloat162*>(g_xa_lo)[2 * i]     = hilo2(v.x, v.y, true);
    reinterpret_cast<__nv_bfloat162*>(g_xa_lo)[2 * i + 1] = hilo2(v.z, v.w, true);
}

template <int NCOLS, int WHICH>
__global__ void k_tsplit(const float* __restrict__ W) {
    __shared__ float t[32][33];
    const int n0 = blockIdx.x * 32, k0 = blockIdx.y * 32;
    const int tx = threadIdx.x, ty = threadIdx.y;   // (32, 8)
#pragma unroll
    for (int i = 0; i < 4; ++i)
        t[ty * 4 + i][tx] = W[(size_t)(k0 + ty * 4 + i) * NCOLS + n0 + tx];
    __syncthreads();
    __nv_bfloat16* Hi = WHICH ? g_wot_hi : g_wqkvt_hi;
    __nv_bfloat16* Lo = WHICH ? g_wot_lo : g_wqkvt_lo;
#pragma unroll
    for (int i = 0; i < 4; ++i) {
        float v = t[tx][ty * 4 + i];
        __nv_bfloat16 h = __float2bfloat16(v);
        __nv_bfloat16 l = __float2bfloat16(v - __bfloat162float(h));
        size_t o = (size_t)(n0 + ty * 4 + i) * HID + k0 + tx;
        Hi[o] = h;
        Lo[o] = l;
    }
}

// ---------------------------------------------------------------------------
// HMMA GEMM (projections), 2-stage cp.async + ldmatrix. (unchanged from R7)
// ---------------------------------------------------------------------------
namespace {
constexpr int GBM = 128, GBK = 32, GLDS = 40;
constexpr int GTILE = GBM * GLDS;
constexpr int GSTAGE = 4 * GTILE;
constexpr int GEMM_SMEM = 2 * GSTAGE * 2;         // 81920 B
}

template <int MODE>
__global__ __launch_bounds__(256) void k_gemm(const float* __restrict__ bias,
                                              float* __restrict__ Cout) {
    extern __shared__ __nv_bfloat16 gsm[];

    const int tid  = threadIdx.x;
    const int warp = tid >> 5, lane = tid & 31;
    const int wm = (warp >> 2) * 64;
    const int wn = (warp & 3) * 32;
    const int gi  = lane >> 2;
    const int tig = lane & 3;
    const int m0 = blockIdx.y * GBM;
    const int n0 = blockIdx.x * GBM;

    const int lane7 = lane & 7;
    const int aRow = lane7 + ((lane & 8) ? 8 : 0);
    const int aK   = (lane & 16) ? 8 : 0;
    const int bRow = lane7 + ((lane & 16) ? 8 : 0);
    const int bK   = (lane & 8) ? 8 : 0;

    const __nv_bfloat16* __restrict__ Ah = MODE ? g_oa_hi : g_xa_hi;
    const __nv_bfloat16* __restrict__ Al = MODE ? g_oa_lo : g_xa_lo;
    const __nv_bfloat16* __restrict__ Bh = MODE ? g_wot_hi : g_wqkvt_hi;
    const __nv_bfloat16* __restrict__ Bl = MODE ? g_wot_lo : g_wqkvt_lo;

    const int r0c = tid >> 2, k0c = (tid & 3);
    const int r1c = (tid + 256) >> 2, k1c = (tid & 3);

    auto issue_tile = [&](int kt, int stage) {
        __nv_bfloat16* base = gsm + stage * GSTAGE;
        const int kk = kt * GBK;
#pragma unroll
        for (int c = 0; c < 2; ++c) {
            const int row = c ? r1c : r0c;
            const int kc  = c ? k1c : k0c;
            const uint32_t soff = smem_u32(base + row * GLDS + kc * 8);
            const size_t ga = (size_t)(m0 + row) * HID + kk + kc * 8;
            const size_t gb = (size_t)(n0 + row) * HID + kk + kc * 8;
            cp16(soff,                 Ah + ga);
            cp16(soff + GTILE * 2,     Al + ga);
            cp16(soff + 2 * GTILE * 2, Bh + gb);
            cp16(soff + 3 * GTILE * 2, Bl + gb);
        }
        CP_COMMIT();
    };

    float acc[4][4][4] = {};
    constexpr int NT = HID / GBK;   // 36

    issue_tile(0, 0);

    for (int t = 0; t < NT; ++t) {
        if (t + 1 < NT) {
            issue_tile(t + 1, (t + 1) & 1);
            CP_WAIT(1);
        } else {
            CP_WAIT(0);
        }
        __syncthreads();

        const uint32_t uAh = smem_u32(gsm + (t & 1) * GSTAGE);
        const uint32_t uAl = uAh + GTILE * 2;
        const uint32_t uBh = uAh + 2 * GTILE * 2;
        const uint32_t uBl = uAh + 3 * GTILE * 2;

#pragma unroll
        for (int ks = 0; ks < GBK; ks += 16) {
            uint32_t ah[4][4], al[4][4], b[4][2];
#pragma unroll
            for (int mf = 0; mf < 4; ++mf) {
                const uint32_t off = ((wm + mf * 16 + aRow) * GLDS + ks + aK) * 2;
                ldsm4(ah[mf][0], ah[mf][1], ah[mf][2], ah[mf][3], uAh + off);
                ldsm4(al[mf][0], al[mf][1], al[mf][2], al[mf][3], uAl + off);
            }
#pragma unroll
            for (int np = 0; np < 2; ++np) {
                const uint32_t off = ((wn + np * 16 + bRow) * GLDS + ks + bK) * 2;
                ldsm4(b[2 * np][0], b[2 * np][1], b[2 * np + 1][0], b[2 * np + 1][1], uBh + off);
            }
#pragma unroll
            for (int mf = 0; mf < 4; ++mf)
#pragma unroll
                for (int nf = 0; nf < 4; ++nf) {
                    mma16816(acc[mf][nf], ah[mf], b[nf]);
                    mma16816(acc[mf][nf], al[mf], b[nf]);
                }
#pragma unroll
            for (int np = 0; np < 2; ++np) {
                const uint32_t off = ((wn + np * 16 + bRow) * GLDS + ks + bK) * 2;
                ldsm4(b[2 * np][0], b[2 * np][1], b[2 * np + 1][0], b[2 * np + 1][1], uBl + off);
            }
#pragma unroll
            for (int mf = 0; mf < 4; ++mf)
#pragma unroll
                for (int nf = 0; nf < 4; ++nf)
                    mma16816(acc[mf][nf], ah[mf], b[nf]);
        }
        __syncthreads();
    }

    const float qscale = 0.11785113019775793f;  // 1/sqrt(72)
#pragma unroll
    for (int mf = 0; mf < 4; ++mf) {
#pragma unroll
        for (int nf = 0; nf < 4; ++nf) {
            const int row = m0 + wm + mf * 16 + gi;
            const int col = n0 + wn + nf * 8 + tig * 2;
            const float b0 = bias[col], b1 = bias[col + 1];
            float x0 = acc[mf][nf][0] + b0, y0 = acc[mf][nf][1] + b1;
            float x1 = acc[mf][nf][2] + b0, y1 = acc[mf][nf][3] + b1;
            if (MODE == 0) {
                const int which = n0 / ATT;
                const int rem = col - which * ATT;
                const int h = rem / Dd, d = rem - h * Dd;
                const int bb = row >> 10, tok = row & 1023;
                const int bh = bb * Hh + h;
                if (which < 2) {
                    if (which == 0) { x0 *= qscale; y0 *= qscale; x1 *= qscale; y1 *= qscale; }
                    __nv_bfloat16* Hi = which ? g_kh : g_qh;
                    __nv_bfloat16* Lo = which ? g_kl : g_ql;
                    const size_t o0 = ((size_t)bh * Nn + tok) * DP + d;
                    const size_t o1 = o0 + 8 * DP;
                    *reinterpret_cast<__nv_bfloat162*>(&Hi[o0]) = hilo2(x0, y0, false);
                    *reinterpret_cast<__nv_bfloat162*>(&Lo[o0]) = hilo2(x0, y0, true);
                    *reinterpret_cast<__nv_bfloat162*>(&Hi[o1]) = hilo2(x1, y1, false);
                    *reinterpret_cast<__nv_bfloat162*>(&Lo[o1]) = hilo2(x1, y1, true);
                } else {
                    const size_t b0o = ((size_t)bh * Dd + d) * Nn + tok;
                    const size_t b1o = b0o + Nn;
                    __nv_bfloat16 h0 = __float2bfloat16(x0);
                    __nv_bfloat16 h1 = __float2bfloat16(y0);
                    __nv_bfloat16 h2 = __float2bfloat16(x1);
                    __nv_bfloat16 h3 = __float2bfloat16(y1);
                    g_vth[b0o]     = h0;
                    g_vth[b1o]     = h1;
                    g_vth[b0o + 8] = h2;
                    g_vth[b1o + 8] = h3;
                    g_vtl[b0o]     = __float2bfloat16(x0 - __bfloat162float(h0));
                    g_vtl[b1o]     = __float2bfloat16(y0 - __bfloat162float(h1));
                    g_vtl[b0o + 8] = __float2bfloat16(x1 - __bfloat162float(h2));
                    g_vtl[b1o + 8] = __float2bfloat16(y1 - __bfloat162float(h3));
                }
            } else {
                *reinterpret_cast<float2*>(&Cout[(size_t)row * HID + col]) = make_float2(x0, y0);
                *reinterpret_cast<float2*>(&Cout[(size_t)(row + 8) * HID + col]) = make_float2(x1, y1);
            }
        }
    }
}

// ---------------------------------------------------------------------------
// Flash attention R8: 64-token K/V tiles (86KB smem -> 2 CTAs/SM),
// exp/pack/PV interleaved per k-chunk. Q tile 128 rows.
// ---------------------------------------------------------------------------
namespace {
constexpr int LDSK  = 88;
constexpr int LDSV  = 72;                 // V^T tile: 64 tokens + 8 pad
constexpr int KROWS = 64;                 // K/V tokens per tile
constexpr int QELE  = 128 * LDSK;         // 11264
constexpr int KELE  = KROWS * LDSK;       // 5632
constexpr int VELE  = Dd * LDSV;          // 5184
constexpr int FLASH_SMEM = (2 * QELE + 2 * KELE + 2 * VELE) * 2;   // 88320 B
}

__global__ __launch_bounds__(256, 2) void k_flash() {
    extern __shared__ __nv_bfloat16 sm[];
    __nv_bfloat16* sQh = sm;
    __nv_bfloat16* sQl = sm + QELE;
    __nv_bfloat16* sKh = sm + 2 * QELE;
    __nv_bfloat16* sKl = sm + 2 * QELE + KELE;
    __nv_bfloat16* sVh = sm + 2 * QELE + 2 * KELE;
    __nv_bfloat16* sVl = sm + 2 * QELE + 2 * KELE + VELE;

    const int tid  = threadIdx.x;
    const int warp = tid >> 5, lane = tid & 31;
    const int wm  = warp * 16;
    const int gi  = lane >> 2;
    const int tig = lane & 3;
    const int bh = blockIdx.y;
    const int m0 = blockIdx.x * 128;

    const int lane7 = lane & 7;
    const int aRow = lane7 + ((lane & 8) ? 8 : 0);
    const int aK   = (lane & 16) ? 8 : 0;
    const int bRow = lane7 + ((lane & 16) ? 8 : 0);
    const int bK   = (lane & 8) ? 8 : 0;

    const uint32_t uQh = smem_u32(sQh), uQl = smem_u32(sQl);
    const uint32_t uKh = smem_u32(sKh), uKl = smem_u32(sKl);
    const uint32_t uVh = smem_u32(sVh), uVl = smem_u32(sVl);

    const __nv_bfloat16* __restrict__ Qh = g_qh + (size_t)bh * Nn * DP;
    const __nv_bfloat16* __restrict__ Ql = g_ql + (size_t)bh * Nn * DP;
    const __nv_bfloat16* __restrict__ Kh = g_kh + (size_t)bh * Nn * DP;
    const __nv_bfloat16* __restrict__ Kl = g_kl + (size_t)bh * Nn * DP;
    const __nv_bfloat16* __restrict__ Vh = g_vth + (size_t)bh * Dd * Nn;
    const __nv_bfloat16* __restrict__ Vl = g_vtl + (size_t)bh * Dd * Nn;

    auto issueK = [&](int kt) {
        const int nn = kt * KROWS;
#pragma unroll
        for (int c = 0; c < 3; ++c) {
            const int chunk = tid + c * 256;       // KROWS*10 = 640 chunks
            if (chunk < KROWS * 10) {
                const int row = chunk / 10;
                const int kc  = chunk - row * 10;
                const size_t gk = (size_t)(nn + row) * DP + kc * 8;
                cp16(smem_u32(sKh + row * LDSK + kc * 8), Kh + gk);
                cp16(smem_u32(sKl + row * LDSK + kc * 8), Kl + gk);
            }
        }
        CP_COMMIT();
    };
    auto issueV = [&](int kt) {
        const int nn = kt * KROWS;
#pragma unroll
        for (int c = 0; c < 3; ++c) {
            const int chunk = tid + c * 256;       // Dd*8 = 576 chunks
            if (chunk < Dd * 8) {
                const int row = chunk >> 3;
                const int kc  = chunk & 7;
                const size_t gv = (size_t)row * Nn + nn + kc * 8;
                cp16(smem_u32(sVh + row * LDSV + kc * 8), Vh + gv);
                cp16(smem_u32(sVl + row * LDSV + kc * 8), Vl + gv);
            }
        }
        CP_COMMIT();
    };

    issueK(0);
#pragma unroll
    for (int c = 0; c < 5; ++c) {
        const int chunk = tid + c * 256;
        const int row = chunk / 10;
        const int kc  = chunk - row * 10;
        const int soff = row * LDSK + kc * 8;
        const size_t gq = (size_t)(m0 + row) * DP + kc * 8;
        *reinterpret_cast<uint4*>(&sQh[soff]) = *reinterpret_cast<const uint4*>(&Qh[gq]);
        *reinterpret_cast<uint4*>(&sQl[soff]) = *reinterpret_cast<const uint4*>(&Ql[gq]);
    }

    float m_run0 = -3.4e38f, m_run1 = -3.4e38f;
    float l_run0 = 0.f, l_run1 = 0.f;
    float o[9][4] = {};

    for (int kt = 0; kt < Nn / KROWS; ++kt) {
        CP_WAIT(0);        // K(kt) arrived
        __syncthreads();   // K visible; V buffer free (all warps past prev PV)

        issueV(kt);        // V streams during S-MMA

        // S = Q K^T over 64 cols, 3-pass, ldmatrix
        float s[8][4];
#pragma unroll
        for (int nf = 0; nf < 8; ++nf)
            s[nf][0] = s[nf][1] = s[nf][2] = s[nf][3] = 0.f;
#pragma unroll
        for (int ks = 0; ks < DP; ks += 16) {
            uint32_t aH[4], aL[4], b[2][2];
            const uint32_t aoff = ((wm + aRow) * LDSK + ks + aK) * 2;
            ldsm4(aH[0], aH[1], aH[2], aH[3], uQh + aoff);
            ldsm4(aL[0], aL[1], aL[2], aL[3], uQl + aoff);
#pragma unroll
            for (int np = 0; np < 4; ++np) {
                const uint32_t boff = ((np * 16 + bRow) * LDSK + ks + bK) * 2;
                ldsm4(b[0][0], b[0][1], b[1][0], b[1][1], uKh + boff);
                mma16816(s[2 * np],     aH, b[0]);
                mma16816(s[2 * np],     aL, b[0]);
                mma16816(s[2 * np + 1], aH, b[1]);
                mma16816(s[2 * np + 1], aL, b[1]);
            }
#pragma unroll
            for (int np = 0; np < 4; ++np) {
                const uint32_t boff = ((np * 16 + bRow) * LDSK + ks + bK) * 2;
                ldsm4(b[0][0], b[0][1], b[1][0], b[1][1], uKl + boff);
                mma16816(s[2 * np],     aH, b[0]);
                mma16816(s[2 * np + 1], aH, b[1]);
            }
        }

        // online softmax stats
        float mt0 = -3.4e38f, mt1 = -3.4e38f;
#pragma unroll
        for (int nf = 0; nf < 8; ++nf) {
            mt0 = fmaxf(mt0, fmaxf(s[nf][0], s[nf][1]));
            mt1 = fmaxf(mt1, fmaxf(s[nf][2], s[nf][3]));
        }
        mt0 = fmaxf(mt0, __shfl_xor_sync(0xffffffffu, mt0, 1));
        mt0 = fmaxf(mt0, __shfl_xor_sync(0xffffffffu, mt0, 2));
        mt1 = fmaxf(mt1, __shfl_xor_sync(0xffffffffu, mt1, 1));
        mt1 = fmaxf(mt1, __shfl_xor_sync(0xffffffffu, mt1, 2));
        const float mn0 = fmaxf(m_run0, mt0);
        const float mn1 = fmaxf(m_run1, mt1);
        const float sc0 = __expf(m_run0 - mn0);
        const float sc1 = __expf(m_run1 - mn1);
        m_run0 = mn0;
        m_run1 = mn1;
#pragma unroll
        for (int nf = 0; nf < 9; ++nf) {
            o[nf][0] *= sc0; o[nf][1] *= sc0;
            o[nf][2] *= sc1; o[nf][3] *= sc1;
        }

        CP_WAIT(0);        // V(kt) arrived
        __syncthreads();   // V visible; sK free (all warps past S-MMA)

        if (kt + 1 < Nn / KROWS) issueK(kt + 1);   // K(kt+1) streams during PV

        float ps0 = 0.f, ps1 = 0.f;
        // per k16-chunk: exp + pack + 3-pass PV (p live range = 8 regs)
#pragma unroll
        for (int kc = 0; kc < 4; ++kc) {
            const int nf0 = 2 * kc, nf1 = 2 * kc + 1;
            const float p00 = __expf(s[nf0][0] - mn0), p01 = __expf(s[nf0][1] - mn0);
            const float p02 = __expf(s[nf0][2] - mn1), p03 = __expf(s[nf0][3] - mn1);
            const float p10 = __expf(s[nf1][0] - mn0), p11 = __expf(s[nf1][1] - mn0);
            const float p12 = __expf(s[nf1][2] - mn1), p13 = __expf(s[nf1][3] - mn1);
            ps0 += p00 + p01 + p10 + p11;
            ps1 += p02 + p03 + p12 + p13;
            uint32_t pH[4], pL[4];
            pack_hilo(p00, p01, pH[0], pL[0]);
            pack_hilo(p02, p03, pH[1], pL[1]);
            pack_hilo(p10, p11, pH[2], pL[2]);
            pack_hilo(p12, p13, pH[3], pL[3]);

            uint32_t b[9][2];
#pragma unroll
            for (int np = 0; np < 4; ++np) {
                const uint32_t off = ((np * 16 + bRow) * LDSV + kc * 16 + bK) * 2;
                ldsm4(b[2 * np][0], b[2 * np][1], b[2 * np + 1][0], b[2 * np + 1][1], uVh + off);
            }
            {
                const uint32_t off = ((64 + lane7) * LDSV + kc * 16 + bK) * 2;
                ldsm2(b[8][0], b[8][1], uVh + off);
            }
#pragma unroll
            for (int nf = 0; nf < 9; ++nf) {
                mma16816(o[nf], pH, b[nf]);
                mma16816(o[nf], pL, b[nf]);
            }
#pragma unroll
            for (int np = 0; np < 4; ++np) {
                const uint32_t off = ((np * 16 + bRow) * LDSV + kc * 16 + bK) * 2;
                ldsm4(b[2 * np][0], b[2 * np][1], b[2 * np + 1][0], b[2 * np + 1][1], uVl + off);
            }
            {
                const uint32_t off = ((64 + lane7) * LDSV + kc * 16 + bK) * 2;
                ldsm2(b[8][0], b[8][1], uVl + off);
            }
#pragma unroll
            for (int nf = 0; nf < 9; ++nf)
                mma16816(o[nf], pH, b[nf]);
        }
        ps0 += __shfl_xor_sync(0xffffffffu, ps0, 1);
        ps0 += __shfl_xor_sync(0xffffffffu, ps0, 2);
        ps1 += __shfl_xor_sync(0xffffffffu, ps1, 1);
        ps1 += __shfl_xor_sync(0xffffffffu, ps1, 2);
        l_run0 = l_run0 * sc0 + ps0;
        l_run1 = l_run1 * sc1 + ps1;
    }

    // epilogue
    const float inv0 = 1.0f / l_run0;
    const float inv1 = 1.0f / l_run1;
    const int b = bh >> 4;
    const int h = bh & 15;
    const int tok0 = m0 + wm + gi;
#pragma unroll
    for (int nf = 0; nf < 9; ++nf) {
        const int col = nf * 8 + tig * 2;
        const size_t o0 = ((size_t)(b * Nn + tok0)) * HID + h * Dd + col;
        const size_t o1 = ((size_t)(b * Nn + tok0 + 8)) * HID + h * Dd + col;
        const float x0 = o[nf][0] * inv0, y0 = o[nf][1] * inv0;
        const float x1 = o[nf][2] * inv1, y1 = o[nf][3] * inv1;
        *reinterpret_cast<__nv_bfloat162*>(&g_oa_hi[o0]) = hilo2(x0, y0, false);
        *reinterpret_cast<__nv_bfloat162*>(&g_oa_lo[o0]) = hilo2(x0, y0, true);
        *reinterpret_cast<__nv_bfloat162*>(&g_oa_hi[o1]) = hilo2(x1, y1, false);
        *reinterpret_cast<__nv_bfloat162*>(&g_oa_lo[o1]) = hilo2(x1, y1, true);
    }
}

// ---------------------------------------------------------------------------
extern "C" void kernel_launch(void* const* d_in, const int* in_sizes, int n_in,
                              void* d_out, int out_size) {
    const float* x     = (const float*)d_in[0];
    const float* w_qkv = (const float*)d_in[1];
    const float* b_qkv = (const float*)d_in[2];
    const float* w_out = (const float*)d_in[3];
    const float* b_out = (const float*)d_in[4];
    float* out = (float*)d_out;

    cudaFuncSetAttribute(k_flash, cudaFuncAttributeMaxDynamicSharedMemorySize, FLASH_SMEM);
    cudaFuncSetAttribute(k_gemm<0>, cudaFuncAttributeMaxDynamicSharedMemorySize, GEMM_SMEM);
    cudaFuncSetAttribute(k_gemm<1>, cudaFuncAttributeMaxDynamicSharedMemorySize, GEMM_SMEM);

    const int n4 = MTOK * HID / 4;

    // prep
    k_zpad<<<(BHEAD * Nn + 255) / 256, 256>>>();
    k_split<<<(n4 + 255) / 256, 256>>>(x);
    k_tsplit<QKVN, 0><<<dim3(QKVN / 32, HID / 32), dim3(32, 8)>>>(w_qkv);
    k_tsplit<HID, 1><<<dim3(HID / 32, HID / 32), dim3(32, 8)>>>(w_out);

    // 1. QKV projection -> Q(scaled)/K hi/lo (padded), V^T hi/lo
    k_gemm<0><<<dim3(QKVN / 128, MTOK / 128), 256, GEMM_SMEM>>>(b_qkv, nullptr);

    // 2. fused flash attention -> g_oa hi/lo
    k_flash<<<dim3(Nn / 128, BHEAD), 256, FLASH_SMEM>>>();

    // 3. output projection
    k_gemm<1><<<dim3(HID / 128, MTOK / 128), 256, GEMM_SMEM>>>(b_out, out);
}